// round 1
// baseline (speedup 1.0000x reference)
#include <cuda_runtime.h>
#include <math.h>

#define BATCH 64
#define SEQ   512
#define IDIM  1024
#define HDIM  1024
#define G4    4096                 // 4*H
#define M_TOTAL (BATCH*SEQ)        // 32768

// Scratch (no cudaMalloc allowed): 512MB xg buffer + ping-pong h state + c state
__device__ float g_xg[(size_t)M_TOTAL * G4];
__device__ float g_h[2][(size_t)BATCH * HDIM];
__device__ float g_c[(size_t)BATCH * HDIM];

// ---------------------------------------------------------------------------
// Zero the recurrent state
// ---------------------------------------------------------------------------
__global__ void init_state_kernel() {
    int i = blockIdx.x * blockDim.x + threadIdx.x;
    if (i < BATCH * HDIM) {
        g_h[0][i] = 0.f;
        g_h[1][i] = 0.f;
        g_c[i]    = 0.f;
    }
}

// ---------------------------------------------------------------------------
// Input projection GEMM: g_xg[m][n] = sum_k x[m][k] * W_ih[n][k] + bih[n]+bhh[n]
// Tile 128(M) x 64(N), K-chunk 32. 256 threads, 8x4 microtile per thread.
// ---------------------------------------------------------------------------
__global__ void gemm_input_kernel(const float* __restrict__ x,
                                  const float* __restrict__ Wih,
                                  const float* __restrict__ bih,
                                  const float* __restrict__ bhh) {
    __shared__ __align__(16) float As[128 * 36];  // pad 32->36 floats per row
    __shared__ __align__(16) float Ws[64 * 36];

    const int tid = threadIdx.x;
    const int tc  = tid & 15;   // n-group (16 groups, cols strided by 16)
    const int tb  = tid >> 4;   // m-group (16 groups of 8 rows)
    const int mt  = blockIdx.x;
    const int nt  = blockIdx.y;

    const float* Abase = x   + (size_t)mt * 128 * IDIM;
    const float* Wbase = Wih + (size_t)nt * 64  * IDIM;

    float acc[8][4];
#pragma unroll
    for (int i = 0; i < 8; i++)
#pragma unroll
        for (int j = 0; j < 4; j++) acc[i][j] = 0.f;

    for (int kc = 0; kc < IDIM / 32; kc++) {
        __syncthreads();  // previous-iteration smem reads complete
        // Cooperative load A tile: 128 rows x 32 k = 1024 float4
#pragma unroll
        for (int p = 0; p < 4; p++) {
            int idx = tid + p * 256;
            int r = idx >> 3, c4 = idx & 7;
            float4 v = *(const float4*)(Abase + (size_t)r * IDIM + kc * 32 + c4 * 4);
            *(float4*)(As + r * 36 + c4 * 4) = v;
        }
        // Cooperative load W tile: 64 rows x 32 k = 512 float4
#pragma unroll
        for (int p = 0; p < 2; p++) {
            int idx = tid + p * 256;
            int r = idx >> 3, c4 = idx & 7;
            float4 v = *(const float4*)(Wbase + (size_t)r * IDIM + kc * 32 + c4 * 4);
            *(float4*)(Ws + r * 36 + c4 * 4) = v;
        }
        __syncthreads();

#pragma unroll
        for (int kk4 = 0; kk4 < 8; kk4++) {
            float4 wv[4];
#pragma unroll
            for (int j = 0; j < 4; j++)
                wv[j] = *(const float4*)(Ws + (tc + j * 16) * 36 + kk4 * 4);
#pragma unroll
            for (int i = 0; i < 8; i++) {
                float4 av = *(const float4*)(As + (tb * 8 + i) * 36 + kk4 * 4);
#pragma unroll
                for (int j = 0; j < 4; j++) {
                    acc[i][j] += av.x * wv[j].x;
                    acc[i][j] += av.y * wv[j].y;
                    acc[i][j] += av.z * wv[j].z;
                    acc[i][j] += av.w * wv[j].w;
                }
            }
        }
    }

    // Epilogue: add bias, store to g_xg
#pragma unroll
    for (int j = 0; j < 4; j++) {
        int n = nt * 64 + tc + j * 16;
        float bias = bih[n] + bhh[n];
#pragma unroll
        for (int i = 0; i < 8; i++) {
            int m = mt * 128 + tb * 8 + i;
            g_xg[(size_t)m * G4 + n] = acc[i][j] + bias;
        }
    }
}

// ---------------------------------------------------------------------------
// One LSTM timestep: gates = xg[:,t,:] + h @ W_hh^T, then cell update.
// Grid: 128 blocks; block j owns h-columns [j*8, j*8+8) across all 4 gates
// (32 W_hh rows). 256 threads; each thread: 4 batches x 2 gate-rows.
// h state ping-pongs between g_h[0]/g_h[1] (no intra-step races).
// ---------------------------------------------------------------------------
__global__ void lstm_step_kernel(const float* __restrict__ Whh,
                                 float* __restrict__ Hout,
                                 float* __restrict__ Cout,
                                 int t) {
    __shared__ __align__(16) float sm[64 * 64];  // h tile, later reused for gates

    const int tid = threadIdx.x;
    const int tc  = tid & 15;
    const int tb  = tid >> 4;
    const int blk = blockIdx.x;
    const int pin  = t & 1;
    const int pout = pin ^ 1;

    const int lc0 = tc;          // local gate-col 0..15  -> gates i (0..7), f (8..15)
    const int lc1 = tc + 16;     // local gate-col 16..31 -> gates g, o
    const int row0 = (lc0 >> 3) * HDIM + blk * 8 + (lc0 & 7);
    const int row1 = (lc1 >> 3) * HDIM + blk * 8 + (lc1 & 7);
    const float* w0 = Whh + (size_t)row0 * HDIM;
    const float* w1 = Whh + (size_t)row1 * HDIM;
    const float* hin = g_h[pin];

    float acc[4][2];
#pragma unroll
    for (int i = 0; i < 4; i++) { acc[i][0] = 0.f; acc[i][1] = 0.f; }

    for (int kt = 0; kt < HDIM / 64; kt++) {
        __syncthreads();
        // Load h tile [64 batches][64 k] cooperatively
#pragma unroll
        for (int p = 0; p < 4; p++) {
            int idx = tid + p * 256;
            int r = idx >> 4, c4 = idx & 15;
            float4 v = *(const float4*)(hin + (size_t)r * HDIM + kt * 64 + c4 * 4);
            *(float4*)(sm + r * 64 + c4 * 4) = v;
        }
        __syncthreads();

#pragma unroll
        for (int kk4 = 0; kk4 < 16; kk4++) {
            float4 wv0 = *(const float4*)(w0 + kt * 64 + kk4 * 4);
            float4 wv1 = *(const float4*)(w1 + kt * 64 + kk4 * 4);
#pragma unroll
            for (int i = 0; i < 4; i++) {
                float4 hv = *(const float4*)(sm + (tb * 4 + i) * 64 + kk4 * 4);
                acc[i][0] += hv.x * wv0.x + hv.y * wv0.y + hv.z * wv0.z + hv.w * wv0.w;
                acc[i][1] += hv.x * wv1.x + hv.y * wv1.y + hv.z * wv1.z + hv.w * wv1.w;
            }
        }
    }

    __syncthreads();  // all sm (h-tile) reads done before reuse as gate buffer

    // Gates (pre-activation, xg already includes both biases) -> smem [32][64]
#pragma unroll
    for (int i = 0; i < 4; i++) {
        int b = tb * 4 + i;
        size_t xbase = ((size_t)b * SEQ + t) * G4;
        sm[lc0 * 64 + b] = acc[i][0] + g_xg[xbase + row0];
        sm[lc1 * 64 + b] = acc[i][1] + g_xg[xbase + row1];
    }
    __syncthreads();

    // Cell update: 8 h-cols x 64 batches = 512 cells, 2 per thread
#pragma unroll
    for (int p = 0; p < 2; p++) {
        int cid = tid + p * 256;
        int b  = cid & 63;
        int cc = cid >> 6;                 // 0..7
        float gi = sm[(cc)      * 64 + b];
        float gf = sm[(8 + cc)  * 64 + b];
        float gg = sm[(16 + cc) * 64 + b];
        float go = sm[(24 + cc) * 64 + b];

        float iv = 1.f / (1.f + expf(-gi));
        float fv = 1.f / (1.f + expf(-gf));
        float gv = tanhf(gg);
        float ov = 1.f / (1.f + expf(-go));

        int hcol = blk * 8 + cc;
        float cold = g_c[b * HDIM + hcol];
        float cnew = fv * cold + iv * gv;
        float hnew = ov * tanhf(cnew);

        g_c[b * HDIM + hcol]        = cnew;
        g_h[pout][b * HDIM + hcol]  = hnew;

        size_t oidx = ((size_t)b * SEQ + t) * HDIM + hcol;
        Hout[oidx] = hnew;
        Cout[oidx] = cnew;
    }
}

// ---------------------------------------------------------------------------
// Launch: init state, input GEMM, then 512 sequential fused step kernels.
// Graph-capturable: kernel launches only, no sync, no allocation.
// ---------------------------------------------------------------------------
extern "C" void kernel_launch(void* const* d_in, const int* in_sizes, int n_in,
                              void* d_out, int out_size) {
    const float* x    = (const float*)d_in[0];
    const float* Wih  = (const float*)d_in[1];
    const float* Whh  = (const float*)d_in[2];
    const float* bih  = (const float*)d_in[3];
    const float* bhh  = (const float*)d_in[4];

    float* Hout = (float*)d_out;                                   // [B,S,H]
    float* Cout = Hout + (size_t)BATCH * SEQ * HDIM;               // [B,S,H]

    init_state_kernel<<<(BATCH * HDIM + 255) / 256, 256>>>();

    dim3 g1(M_TOTAL / 128, G4 / 64);   // 256 x 64 blocks
    gemm_input_kernel<<<g1, 256>>>(x, Wih, bih, bhh);

    for (int t = 0; t < SEQ; t++) {
        lstm_step_kernel<<<HDIM / 8, 256>>>(Whh, Hout, Cout, t);
    }
}

// round 2
// speedup vs baseline: 2.1706x; 2.1706x over previous
#include <cuda_runtime.h>
#include <math.h>

#define BATCH 64
#define SEQ   512
#define IDIM  1024
#define HDIM  1024
#define G4    4096                 // 4*H
#define M_TOTAL (BATCH*SEQ)        // 32768

// Scratch (no cudaMalloc allowed)
__device__ float g_xg[(size_t)M_TOTAL * G4];
__device__ float g_h[2][(size_t)BATCH * HDIM];   // layout [b][hcol]
__device__ float g_c[(size_t)BATCH * HDIM];      // layout [hcol][b]

// ---------------------------------------------------------------------------
// Zero the recurrent state
// ---------------------------------------------------------------------------
__global__ void init_state_kernel() {
    int i = blockIdx.x * blockDim.x + threadIdx.x;
    if (i < BATCH * HDIM) {
        g_h[0][i] = 0.f;
        g_h[1][i] = 0.f;
        g_c[i]    = 0.f;
    }
}

// ---------------------------------------------------------------------------
// MUFU-free activations: Eigen-style rational minimax tanh + bit-trick rcp.
// All FMA/ALU pipe — avoids the 0.5 MUFU/cyc/SM bottleneck (10 MUFU/cell).
// ---------------------------------------------------------------------------
__device__ __forceinline__ float fast_rcp(float q) {
    // q > 0 (denominator of tanh rational is strictly positive)
    float r = __uint_as_float(0x7EF311C2u - __float_as_uint(q));
    r = r * (2.0f - q * r);
    r = r * (2.0f - q * r);
    r = r * (2.0f - q * r);
    return r;
}

__device__ __forceinline__ float fast_tanh(float x) {
    x = fminf(fmaxf(x, -7.90531110763549805f), 7.90531110763549805f);
    float s = x * x;
    float p = fmaf(s, -2.76076847742355e-16f, 2.00018790482477e-13f);
    p = fmaf(p, s, -8.60467152213735e-11f);
    p = fmaf(p, s,  5.12229709037114e-08f);
    p = fmaf(p, s,  1.48572235717979e-05f);
    p = fmaf(p, s,  6.37261928875436e-04f);
    p = fmaf(p, s,  4.89352455891786e-03f);
    p = x * p;
    float q = fmaf(s, 1.19825839466702e-06f, 1.18534705686654e-04f);
    q = fmaf(q, s, 2.26843463243900e-03f);
    q = fmaf(q, s, 4.89352518554385e-03f);
    return p * fast_rcp(q);
}

__device__ __forceinline__ float fast_sigmoid(float x) {
    return fmaf(fast_tanh(0.5f * x), 0.5f, 0.5f);
}

// ---------------------------------------------------------------------------
// Input projection GEMM: g_xg[m][n] = sum_k x[m][k] * W_ih[n][k] + bih[n]+bhh[n]
// Tile 128(M) x 64(N), K-chunk 32. 256 threads, 8x4 microtile per thread.
// ---------------------------------------------------------------------------
__global__ void gemm_input_kernel(const float* __restrict__ x,
                                  const float* __restrict__ Wih,
                                  const float* __restrict__ bih,
                                  const float* __restrict__ bhh) {
    __shared__ __align__(16) float As[128 * 36];
    __shared__ __align__(16) float Ws[64 * 36];

    const int tid = threadIdx.x;
    const int tc  = tid & 15;
    const int tb  = tid >> 4;
    const int mt  = blockIdx.x;
    const int nt  = blockIdx.y;

    const float* Abase = x   + (size_t)mt * 128 * IDIM;
    const float* Wbase = Wih + (size_t)nt * 64  * IDIM;

    float acc[8][4];
#pragma unroll
    for (int i = 0; i < 8; i++)
#pragma unroll
        for (int j = 0; j < 4; j++) acc[i][j] = 0.f;

    for (int kc = 0; kc < IDIM / 32; kc++) {
        __syncthreads();
#pragma unroll
        for (int p = 0; p < 4; p++) {
            int idx = tid + p * 256;
            int r = idx >> 3, c4 = idx & 7;
            float4 v = *(const float4*)(Abase + (size_t)r * IDIM + kc * 32 + c4 * 4);
            *(float4*)(As + r * 36 + c4 * 4) = v;
        }
#pragma unroll
        for (int p = 0; p < 2; p++) {
            int idx = tid + p * 256;
            int r = idx >> 3, c4 = idx & 7;
            float4 v = *(const float4*)(Wbase + (size_t)r * IDIM + kc * 32 + c4 * 4);
            *(float4*)(Ws + r * 36 + c4 * 4) = v;
        }
        __syncthreads();

#pragma unroll
        for (int kk4 = 0; kk4 < 8; kk4++) {
            float4 wv[4];
#pragma unroll
            for (int j = 0; j < 4; j++)
                wv[j] = *(const float4*)(Ws + (tc + j * 16) * 36 + kk4 * 4);
#pragma unroll
            for (int i = 0; i < 8; i++) {
                float4 av = *(const float4*)(As + (tb * 8 + i) * 36 + kk4 * 4);
#pragma unroll
                for (int j = 0; j < 4; j++) {
                    acc[i][j] += av.x * wv[j].x;
                    acc[i][j] += av.y * wv[j].y;
                    acc[i][j] += av.z * wv[j].z;
                    acc[i][j] += av.w * wv[j].w;
                }
            }
        }
    }

#pragma unroll
    for (int j = 0; j < 4; j++) {
        int n = nt * 64 + tc + j * 16;
        float bias = bih[n] + bhh[n];
#pragma unroll
        for (int i = 0; i < 8; i++) {
            int m = mt * 128 + tb * 8 + i;
            g_xg[(size_t)m * G4 + n] = acc[i][j] + bias;
        }
    }
}

// ---------------------------------------------------------------------------
// One LSTM timestep.
// Grid: 256 blocks. Block j owns h-columns [j*4, j*4+4) across all 4 gates
// = 16 W_hh rows (row tx: gate = tx>>2, hl = tx&3).
// 256 threads as (tx=row 0..15, ty=batch-group 0..15): 1 row x 4 batches.
// Inner loop per k4: 5 LDS.128 + 16 FFMA -> FFMA-rate bound.
// Cell update is MUFU-free.
// ---------------------------------------------------------------------------
__global__ void lstm_step_kernel(const float* __restrict__ Whh,
                                 float* __restrict__ Hout,
                                 float* __restrict__ Cout,
                                 int t) {
    __shared__ __align__(16) float sh[64 * 132];   // h chunk [64][128] padded
    __shared__ __align__(16) float ws[16 * 132];   // W chunk [16][128] padded

    const int tid = threadIdx.x;
    const int tx  = tid & 15;    // local gate-row
    const int ty  = tid >> 4;    // batch group (4 batches)
    const int blk = blockIdx.x;  // h-cols [blk*4, blk*4+4)
    const int pin  = t & 1;
    const int pout = pin ^ 1;

    const int grow = (tx >> 2) * HDIM + blk * 4 + (tx & 3);  // global W row
    const float* hin = g_h[pin];

    float acc[4] = {0.f, 0.f, 0.f, 0.f};

    for (int kt = 0; kt < 8; kt++) {
        __syncthreads();
        // h chunk: [64 batches][128 k]
#pragma unroll
        for (int p = 0; p < 8; p++) {
            int pos = tid + p * 256;
            int b = pos >> 5, c4 = pos & 31;
            float4 v = *(const float4*)(hin + (size_t)b * HDIM + kt * 128 + c4 * 4);
            *(float4*)(sh + b * 132 + c4 * 4) = v;
        }
        // W chunk: [16 rows][128 k]
#pragma unroll
        for (int p = 0; p < 2; p++) {
            int pos = tid + p * 256;
            int r = pos >> 5, c4 = pos & 31;
            int gr = (r >> 2) * HDIM + blk * 4 + (r & 3);
            float4 v = *(const float4*)(Whh + (size_t)gr * HDIM + kt * 128 + c4 * 4);
            *(float4*)(ws + r * 132 + c4 * 4) = v;
        }
        __syncthreads();

#pragma unroll 8
        for (int k4 = 0; k4 < 32; k4++) {
            float4 w = *(const float4*)(ws + tx * 132 + k4 * 4);
#pragma unroll
            for (int i = 0; i < 4; i++) {
                float4 h = *(const float4*)(sh + (ty * 4 + i) * 132 + k4 * 4);
                acc[i] += w.x * h.x;
                acc[i] += w.y * h.y;
                acc[i] += w.z * h.z;
                acc[i] += w.w * h.w;
            }
        }
    }

    __syncthreads();  // all sh reads complete; reuse sh as gate buffer [16][68]

#pragma unroll
    for (int i = 0; i < 4; i++) {
        int b = ty * 4 + i;
        float xv = g_xg[((size_t)b * SEQ + t) * G4 + grow];
        sh[tx * 68 + b] = acc[i] + xv;
    }
    __syncthreads();

    // Cell update: hl = tid&3 (consecutive lanes -> consecutive h-cols), b = tid>>2
    {
        const int hl = tid & 3;
        const int b  = tid >> 2;
        float gi = sh[(0  + hl) * 68 + b];
        float gf = sh[(4  + hl) * 68 + b];
        float gg = sh[(8  + hl) * 68 + b];
        float go = sh[(12 + hl) * 68 + b];

        float iv = fast_sigmoid(gi);
        float fv = fast_sigmoid(gf);
        float gv = fast_tanh(gg);
        float ov = fast_sigmoid(go);

        const int hcol = blk * 4 + hl;
        float cold = g_c[hcol * BATCH + b];
        float cnew = fv * cold + iv * gv;
        float hnew = ov * fast_tanh(cnew);

        g_c[hcol * BATCH + b]              = cnew;
        g_h[pout][(size_t)b * HDIM + hcol] = hnew;

        size_t oidx = ((size_t)b * SEQ + t) * HDIM + hcol;
        Hout[oidx] = hnew;
        Cout[oidx] = cnew;
    }
}

// ---------------------------------------------------------------------------
extern "C" void kernel_launch(void* const* d_in, const int* in_sizes, int n_in,
                              void* d_out, int out_size) {
    const float* x    = (const float*)d_in[0];
    const float* Wih  = (const float*)d_in[1];
    const float* Whh  = (const float*)d_in[2];
    const float* bih  = (const float*)d_in[3];
    const float* bhh  = (const float*)d_in[4];

    float* Hout = (float*)d_out;
    float* Cout = Hout + (size_t)BATCH * SEQ * HDIM;

    init_state_kernel<<<(BATCH * HDIM + 255) / 256, 256>>>();

    dim3 g1(M_TOTAL / 128, G4 / 64);
    gemm_input_kernel<<<g1, 256>>>(x, Wih, bih, bhh);

    for (int t = 0; t < SEQ; t++) {
        lstm_step_kernel<<<HDIM / 4, 256>>>(Whh, Hout, Cout, t);
    }
}

// round 5
// speedup vs baseline: 3.0133x; 1.3882x over previous
#include <cuda_runtime.h>
#include <cuda_bf16.h>
#include <stdint.h>

#define BATCH 64
#define SEQ   512
#define IDIM  1024
#define HDIM  1024
#define G4    4096
#define M_TOTAL (BATCH*SEQ)

// ---------------- scratch (no cudaMalloc allowed) ----------------
__device__ float g_xg[(size_t)M_TOTAL * G4];
__device__ __align__(16) __nv_bfloat16 g_x_hi[(size_t)M_TOTAL * IDIM];
__device__ __align__(16) __nv_bfloat16 g_x_lo[(size_t)M_TOTAL * IDIM];
__device__ __align__(16) __nv_bfloat16 g_Wih_hi[(size_t)G4 * IDIM];
__device__ __align__(16) __nv_bfloat16 g_Wih_lo[(size_t)G4 * IDIM];
__device__ __align__(16) __nv_bfloat16 g_Wr_hi[(size_t)G4 * HDIM];   // rearranged W_hh
__device__ __align__(16) __nv_bfloat16 g_Wr_lo[(size_t)G4 * HDIM];
__device__ __align__(16) __nv_bfloat16 g_hb_hi[2][BATCH * HDIM];
__device__ __align__(16) __nv_bfloat16 g_hb_lo[2][BATCH * HDIM];
__device__ float g_c[BATCH * HDIM];

// ---------------- PTX helpers (base compute_103-safe: sm_80 era) ----------
__device__ __forceinline__ uint32_t smem_u32(const void* p) {
    return (uint32_t)__cvta_generic_to_shared(p);
}
__device__ __forceinline__ void ldmx4(uint32_t r[4], uint32_t addr) {
    asm volatile("ldmatrix.sync.aligned.m8n8.x4.shared.b16 {%0,%1,%2,%3}, [%4];"
        : "=r"(r[0]), "=r"(r[1]), "=r"(r[2]), "=r"(r[3]) : "r"(addr));
}
__device__ __forceinline__ void mma16816(float c[4], const uint32_t a[4],
                                         uint32_t b0, uint32_t b1) {
    asm volatile("mma.sync.aligned.m16n8k16.row.col.f32.bf16.bf16.f32 "
        "{%0,%1,%2,%3}, {%4,%5,%6,%7}, {%8,%9}, {%0,%1,%2,%3};"
        : "+f"(c[0]), "+f"(c[1]), "+f"(c[2]), "+f"(c[3])
        : "r"(a[0]), "r"(a[1]), "r"(a[2]), "r"(a[3]), "r"(b0), "r"(b1));
}
__device__ __forceinline__ void cp16(uint32_t dst, const void* src) {
    asm volatile("cp.async.cg.shared.global [%0], [%1], 16;" :: "r"(dst), "l"(src));
}
#define CP_COMMIT() asm volatile("cp.async.commit_group;" ::: "memory")
#define CP_WAIT1()  asm volatile("cp.async.wait_group 1;" ::: "memory")

// ---------------- MUFU-free activations ----------------
__device__ __forceinline__ float fast_rcp(float q) {
    float r = __uint_as_float(0x7EF311C2u - __float_as_uint(q));
    r = r * (2.0f - q * r);
    r = r * (2.0f - q * r);
    r = r * (2.0f - q * r);
    return r;
}
__device__ __forceinline__ float fast_tanh(float x) {
    x = fminf(fmaxf(x, -7.90531110763549805f), 7.90531110763549805f);
    float s = x * x;
    float p = fmaf(s, -2.76076847742355e-16f, 2.00018790482477e-13f);
    p = fmaf(p, s, -8.60467152213735e-11f);
    p = fmaf(p, s,  5.12229709037114e-08f);
    p = fmaf(p, s,  1.48572235717979e-05f);
    p = fmaf(p, s,  6.37261928875436e-04f);
    p = fmaf(p, s,  4.89352455891786e-03f);
    p = x * p;
    float q = fmaf(s, 1.19825839466702e-06f, 1.18534705686654e-04f);
    q = fmaf(q, s, 2.26843463243900e-03f);
    q = fmaf(q, s, 4.89352518554385e-03f);
    return p * fast_rcp(q);
}
__device__ __forceinline__ float fast_sigmoid(float x) {
    return fmaf(fast_tanh(0.5f * x), 0.5f, 0.5f);
}

// ---------------- init + converts ----------------
__global__ void init_state_kernel() {
    int i = blockIdx.x * blockDim.x + threadIdx.x;
    if (i < BATCH * HDIM) {
        __nv_bfloat16 z = __float2bfloat16(0.f);
        g_hb_hi[0][i] = z; g_hb_hi[1][i] = z;
        g_hb_lo[0][i] = z; g_hb_lo[1][i] = z;
        g_c[i] = 0.f;
    }
}
__global__ void convert_x_kernel(const float* __restrict__ x) {
    size_t i = (size_t)blockIdx.x * blockDim.x + threadIdx.x;
    if (i >= (size_t)M_TOTAL * IDIM) return;
    float v = x[i];
    __nv_bfloat16 h = __float2bfloat16(v);
    g_x_hi[i] = h;
    g_x_lo[i] = __float2bfloat16(v - __bfloat162float(h));
}
__global__ void convert_wih_kernel(const float* __restrict__ W) {
    size_t i = (size_t)blockIdx.x * blockDim.x + threadIdx.x;
    if (i >= (size_t)G4 * IDIM) return;
    float v = W[i];
    __nv_bfloat16 h = __float2bfloat16(v);
    g_Wih_hi[i] = h;
    g_Wih_lo[i] = __float2bfloat16(v - __bfloat162float(h));
}
// W_hh rearrange: out row = m*128 + lg; gate = lg>>5; in row = gate*1024 + m*32 + (lg&31)
__global__ void convert_whh_kernel(const float* __restrict__ Whh) {
    size_t idx = (size_t)blockIdx.x * blockDim.x + threadIdx.x;
    if (idx >= (size_t)G4 * HDIM) return;
    int out_row = (int)(idx >> 10);
    int k  = (int)(idx & 1023);
    int m  = out_row >> 7;
    int lg = out_row & 127;
    int in_row = (lg >> 5) * HDIM + m * 32 + (lg & 31);
    float v = Whh[(size_t)in_row * HDIM + k];
    __nv_bfloat16 h = __float2bfloat16(v);
    g_Wr_hi[idx] = h;
    g_Wr_lo[idx] = __float2bfloat16(v - __bfloat162float(h));
}

// ---------------- input projection GEMM (split-bf16 HMMA) ----------------
// xg[m][n] = x[m][:] . Wih[n][:] + bih[n]+bhh[n]; M=32768, N=4096, K=1024
// Block 128x128, K-chunk 32 (32 chunks), 3-stage cp.async. Warp tile 64x32.
#define GI_STRIDE 40                       // elems per smem row (80B)
#define GI_AHI   0
#define GI_ALO   (128*GI_STRIDE*2)         // 10240
#define GI_BHI   (2*128*GI_STRIDE*2)       // 20480
#define GI_BLO   (3*128*GI_STRIDE*2)       // 30720
#define GI_STAGE (4*128*GI_STRIDE*2)       // 40960
#define GI_SMEM  (3*GI_STAGE)              // 122880

__global__ void __launch_bounds__(256, 1)
gemm_input_tc(const float* __restrict__ bih, const float* __restrict__ bhh) {
    extern __shared__ char smem[];
    const uint32_t sb = smem_u32(smem);
    const int tid = threadIdx.x, wid = tid >> 5, lane = tid & 31;
    const int mbase = blockIdx.x * 128;
    const int nbase = blockIdx.y * 128;
    const int wm = wid & 1, wn = wid >> 1;

    float acc[4][4][4] = {};

#define GI_ISSUE(i) do {                                                      \
    uint32_t st = sb + ((i) % 3) * GI_STAGE;                                  \
    _Pragma("unroll")                                                         \
    for (int p = 0; p < 2; p++) {                                             \
        int u = tid + p * 256; int r = u >> 2, c = u & 3;                     \
        size_t g = (size_t)(mbase + r) * IDIM + (size_t)(i) * 32 + c * 8;     \
        cp16(st + GI_AHI + r * 80 + c * 16, g_x_hi + g);                      \
        cp16(st + GI_ALO + r * 80 + c * 16, g_x_lo + g);                      \
    }                                                                         \
    _Pragma("unroll")                                                         \
    for (int p = 0; p < 2; p++) {                                             \
        int u = tid + p * 256; int r = u >> 2, c = u & 3;                     \
        size_t g = (size_t)(nbase + r) * IDIM + (size_t)(i) * 32 + c * 8;     \
        cp16(st + GI_BHI + r * 80 + c * 16, g_Wih_hi + g);                    \
        cp16(st + GI_BLO + r * 80 + c * 16, g_Wih_lo + g);                    \
    }                                                                         \
} while (0)

    GI_ISSUE(0); CP_COMMIT();
    GI_ISSUE(1); CP_COMMIT();

    for (int i = 0; i < 32; i++) {
        CP_WAIT1();
        __syncthreads();
        if (i + 2 < 32) GI_ISSUE(i + 2);
        CP_COMMIT();

        uint32_t st = sb + (i % 3) * GI_STAGE;
#pragma unroll
        for (int kk = 0; kk < 2; kk++) {
            const int colb = kk * 16 + ((lane >> 4) << 3);
            uint32_t ah[4][4], al[4][4], bh[2][4], bl[2][4];
#pragma unroll
            for (int mt = 0; mt < 4; mt++) {
                int row = wm * 64 + mt * 16 + (lane & 15);
                uint32_t a = st + GI_AHI + row * 80 + colb * 2;
                ldmx4(ah[mt], a);
                ldmx4(al[mt], a + (GI_ALO - GI_AHI));
            }
#pragma unroll
            for (int bt = 0; bt < 2; bt++) {
                int row = wn * 32 + bt * 16 + (lane & 15);
                uint32_t a = st + GI_BHI + row * 80 + colb * 2;
                ldmx4(bh[bt], a);                    // B tile is [n][k]: non-trans
                ldmx4(bl[bt], a + (GI_BLO - GI_BHI));
            }
#pragma unroll
            for (int mt = 0; mt < 4; mt++)
#pragma unroll
                for (int nt = 0; nt < 4; nt++) {
                    int bt = nt >> 1, ns = nt & 1;
                    mma16816(acc[mt][nt], ah[mt], bh[bt][ns], bh[bt][ns + 2]);
                    mma16816(acc[mt][nt], ah[mt], bl[bt][ns], bl[bt][ns + 2]);
                    mma16816(acc[mt][nt], al[mt], bh[bt][ns], bh[bt][ns + 2]);
                }
        }
    }

    // Epilogue: add bias, write g_xg
#pragma unroll
    for (int mt = 0; mt < 4; mt++) {
        int m0 = mbase + wm * 64 + mt * 16 + (lane >> 2);
#pragma unroll
        for (int nt = 0; nt < 4; nt++) {
            int n = nbase + wn * 32 + nt * 8 + (lane & 3) * 2;
            float b0 = bih[n] + bhh[n];
            float b1 = bih[n + 1] + bhh[n + 1];
            *(float2*)(g_xg + (size_t)m0 * G4 + n) =
                make_float2(acc[mt][nt][0] + b0, acc[mt][nt][1] + b1);
            *(float2*)(g_xg + (size_t)(m0 + 8) * G4 + n) =
                make_float2(acc[mt][nt][2] + b0, acc[mt][nt][3] + b1);
        }
    }
}

// ---------------- LSTM step (split-bf16 HMMA) ----------------
// Grid 64: blkM = hcol tile (32 cols x 4 gates = 128 W rows), blkN = batch half (32).
// D[128 x 32] over K=1024, K-chunk 64 (16 chunks), 3-stage cp.async.
// Warps 4(M) x 2(N): warp tile 32 x 16. Warp wm holds gate wm.
#define ST_STRIDE 72                          // elems (144B)
#define ST_WHI   0
#define ST_WLO   (128*ST_STRIDE*2)            // 18432
#define ST_HHI   (2*128*ST_STRIDE*2)          // 36864
#define ST_HLO   (ST_HHI + 32*ST_STRIDE*2)    // 41472
#define ST_STAGE (ST_HLO + 32*ST_STRIDE*2)    // 46080
#define ST_SMEM  (3*ST_STAGE)                 // 138240

__global__ void __launch_bounds__(256, 1)
lstm_step_tc(float* __restrict__ Hout, float* __restrict__ Cout, int t) {
    extern __shared__ char smem[];
    const uint32_t sb = smem_u32(smem);
    const int tid = threadIdx.x, wid = tid >> 5, lane = tid & 31;
    const int blkM = blockIdx.x & 31;
    const int blkN = blockIdx.x >> 5;
    const int pin = t & 1, pout = pin ^ 1;
    const int wm = wid & 3, wn = wid >> 2;

    const __nv_bfloat16* hhi = g_hb_hi[pin] + (size_t)blkN * 32 * HDIM;
    const __nv_bfloat16* hlo = g_hb_lo[pin] + (size_t)blkN * 32 * HDIM;

    float acc[2][2][4] = {};

#define ST_ISSUE(i) do {                                                      \
    uint32_t st = sb + ((i) % 3) * ST_STAGE;                                  \
    _Pragma("unroll")                                                         \
    for (int p = 0; p < 4; p++) {                                             \
        int u = tid + p * 256; int r = u >> 3, c = u & 7;                     \
        size_t g = (size_t)(blkM * 128 + r) * HDIM + (size_t)(i) * 64 + c * 8;\
        cp16(st + ST_WHI + r * 144 + c * 16, g_Wr_hi + g);                    \
        cp16(st + ST_WLO + r * 144 + c * 16, g_Wr_lo + g);                    \
    }                                                                         \
    {                                                                         \
        int r = tid >> 3, c = tid & 7;                                        \
        size_t g = (size_t)r * HDIM + (size_t)(i) * 64 + c * 8;               \
        cp16(st + ST_HHI + r * 144 + c * 16, hhi + g);                        \
        cp16(st + ST_HLO + r * 144 + c * 16, hlo + g);                        \
    }                                                                         \
} while (0)

    ST_ISSUE(0); CP_COMMIT();
    ST_ISSUE(1); CP_COMMIT();

    for (int i = 0; i < 16; i++) {
        CP_WAIT1();
        __syncthreads();
        if (i + 2 < 16) ST_ISSUE(i + 2);
        CP_COMMIT();

        uint32_t st = sb + (i % 3) * ST_STAGE;
#pragma unroll
        for (int kk = 0; kk < 4; kk++) {
            const int colb = kk * 16 + ((lane >> 4) << 3);
            uint32_t ah[2][4], al[2][4], bh[4], bl[4];
#pragma unroll
            for (int mt = 0; mt < 2; mt++) {
                int row = wm * 32 + mt * 16 + (lane & 15);
                uint32_t a = st + ST_WHI + row * 144 + colb * 2;
                ldmx4(ah[mt], a);
                ldmx4(al[mt], a + (ST_WLO - ST_WHI));
            }
            {
                int row = wn * 16 + (lane & 15);
                uint32_t a = st + ST_HHI + row * 144 + colb * 2;
                ldmx4(bh, a);                        // H tile is [n][k]: non-trans
                ldmx4(bl, a + (ST_HLO - ST_HHI));
            }
#pragma unroll
            for (int mt = 0; mt < 2; mt++)
#pragma unroll
                for (int ns = 0; ns < 2; ns++) {
                    mma16816(acc[mt][ns], ah[mt], bh[ns], bh[ns + 2]);
                    mma16816(acc[mt][ns], ah[mt], bl[ns], bl[ns + 2]);
                    mma16816(acc[mt][ns], al[mt], bh[ns], bh[ns + 2]);
                }
        }
    }

    __syncthreads();   // stage buffers free; reuse as gate-exchange buffer

    float* sg = (float*)smem;  // [128 rows][36] (rows = gate*32 + hl, cols = local batch)
#pragma unroll
    for (int mt = 0; mt < 2; mt++)
#pragma unroll
        for (int ns = 0; ns < 2; ns++) {
            int row = wm * 32 + mt * 16 + (lane >> 2);
            int col = wn * 16 + ns * 8 + (lane & 3) * 2;
            sg[row * 36 + col]           = acc[mt][ns][0];
            sg[row * 36 + col + 1]       = acc[mt][ns][1];
            sg[(row + 8) * 36 + col]     = acc[mt][ns][2];
            sg[(row + 8) * 36 + col + 1] = acc[mt][ns][3];
        }
    __syncthreads();

    // Cell update: 32 hcols x 32 batches, 4 cells/thread
    {
        const int hl = tid & 31;
        const int bg = tid >> 5;
        const int hcol = blkM * 32 + hl;
#pragma unroll
        for (int j = 0; j < 4; j++) {
            int lb = bg * 4 + j;
            int b  = blkN * 32 + lb;
            size_t xbase = ((size_t)b * SEQ + t) * G4 + blkM * 32 + hl;
            float gi = sg[(0 * 32 + hl) * 36 + lb] + g_xg[xbase];
            float gf = sg[(1 * 32 + hl) * 36 + lb] + g_xg[xbase + 1024];
            float gg = sg[(2 * 32 + hl) * 36 + lb] + g_xg[xbase + 2048];
            float go = sg[(3 * 32 + hl) * 36 + lb] + g_xg[xbase + 3072];

            float iv = fast_sigmoid(gi);
            float fv = fast_sigmoid(gf);
            float gv = fast_tanh(gg);
            float ov = fast_sigmoid(go);

            float cold = g_c[hcol * BATCH + b];
            float cnew = fv * cold + iv * gv;
            float hnew = ov * fast_tanh(cnew);

            g_c[hcol * BATCH + b] = cnew;

            __nv_bfloat16 hh = __float2bfloat16(hnew);
            g_hb_hi[pout][b * HDIM + hcol] = hh;
            g_hb_lo[pout][b * HDIM + hcol] =
                __float2bfloat16(hnew - __bfloat162float(hh));

            size_t oidx = ((size_t)b * SEQ + t) * HDIM + hcol;
            Hout[oidx] = hnew;
            Cout[oidx] = cnew;
        }
    }
}

// ---------------- launch ----------------
extern "C" void kernel_launch(void* const* d_in, const int* in_sizes, int n_in,
                              void* d_out, int out_size) {
    const float* x    = (const float*)d_in[0];
    const float* Wih  = (const float*)d_in[1];
    const float* Whh  = (const float*)d_in[2];
    const float* bih  = (const float*)d_in[3];
    const float* bhh  = (const float*)d_in[4];

    float* Hout = (float*)d_out;
    float* Cout = Hout + (size_t)BATCH * SEQ * HDIM;

    cudaFuncSetAttribute(gemm_input_tc, cudaFuncAttributeMaxDynamicSharedMemorySize, GI_SMEM);
    cudaFuncSetAttribute(lstm_step_tc,  cudaFuncAttributeMaxDynamicSharedMemorySize, ST_SMEM);

    init_state_kernel<<<(BATCH * HDIM + 255) / 256, 256>>>();
    convert_x_kernel<<<(int)(((size_t)M_TOTAL * IDIM + 255) / 256), 256>>>(x);
    convert_wih_kernel<<<(int)(((size_t)G4 * IDIM + 255) / 256), 256>>>(Wih);
    convert_whh_kernel<<<(int)(((size_t)G4 * HDIM + 255) / 256), 256>>>(Whh);

    dim3 g1(M_TOTAL / 128, G4 / 128);   // 256 x 32
    gemm_input_tc<<<g1, 256, GI_SMEM>>>(bih, bhh);

    for (int t = 0; t < SEQ; t++) {
        lstm_step_tc<<<64, 256, ST_SMEM>>>(Hout, Cout, t);
    }
}

// round 6
// speedup vs baseline: 5.9147x; 1.9629x over previous
#include <cuda_runtime.h>
#include <cuda_bf16.h>
#include <stdint.h>

#define BATCH 64
#define SEQ   512
#define IDIM  1024
#define HDIM  1024
#define G4    4096
#define M_TOTAL (BATCH*SEQ)

// ---------------- scratch (no cudaMalloc allowed) ----------------
__device__ float g_xg[(size_t)M_TOTAL * G4];
__device__ __align__(16) __nv_bfloat16 g_x_hi[(size_t)M_TOTAL * IDIM];
__device__ __align__(16) __nv_bfloat16 g_x_lo[(size_t)M_TOTAL * IDIM];
__device__ __align__(16) __nv_bfloat16 g_Wih_hi[(size_t)G4 * IDIM];
__device__ __align__(16) __nv_bfloat16 g_Wih_lo[(size_t)G4 * IDIM];
__device__ __align__(16) __nv_bfloat16 g_Wr_hi[(size_t)G4 * HDIM];   // rearranged W_hh
__device__ __align__(16) __nv_bfloat16 g_Wr_lo[(size_t)G4 * HDIM];
__device__ __align__(16) __nv_bfloat16 g_hb_hi[2][BATCH * HDIM];
__device__ __align__(16) __nv_bfloat16 g_hb_lo[2][BATCH * HDIM];
__device__ float g_c[BATCH * HDIM];
__device__ unsigned g_bar;

// ---------------- PTX helpers (base compute_103-safe) ----------------
__device__ __forceinline__ uint32_t smem_u32(const void* p) {
    return (uint32_t)__cvta_generic_to_shared(p);
}
__device__ __forceinline__ void ldmx4(uint32_t r[4], uint32_t addr) {
    asm volatile("ldmatrix.sync.aligned.m8n8.x4.shared.b16 {%0,%1,%2,%3}, [%4];"
        : "=r"(r[0]), "=r"(r[1]), "=r"(r[2]), "=r"(r[3]) : "r"(addr));
}
__device__ __forceinline__ void mma16816(float c[4], const uint32_t a[4],
                                         uint32_t b0, uint32_t b1) {
    asm volatile("mma.sync.aligned.m16n8k16.row.col.f32.bf16.bf16.f32 "
        "{%0,%1,%2,%3}, {%4,%5,%6,%7}, {%8,%9}, {%0,%1,%2,%3};"
        : "+f"(c[0]), "+f"(c[1]), "+f"(c[2]), "+f"(c[3])
        : "r"(a[0]), "r"(a[1]), "r"(a[2]), "r"(a[3]), "r"(b0), "r"(b1));
}
__device__ __forceinline__ void cp16(uint32_t dst, const void* src) {
    asm volatile("cp.async.cg.shared.global [%0], [%1], 16;" :: "r"(dst), "l"(src));
}
#define CP_COMMIT() asm volatile("cp.async.commit_group;" ::: "memory")
#define CP_WAIT1()  asm volatile("cp.async.wait_group 1;" ::: "memory")
#define CP_WAIT0()  asm volatile("cp.async.wait_group 0;" ::: "memory")

// ---------------- MUFU-free activations ----------------
__device__ __forceinline__ float fast_rcp(float q) {
    float r = __uint_as_float(0x7EF311C2u - __float_as_uint(q));
    r = r * (2.0f - q * r);
    r = r * (2.0f - q * r);
    r = r * (2.0f - q * r);
    return r;
}
__device__ __forceinline__ float fast_tanh(float x) {
    x = fminf(fmaxf(x, -7.90531110763549805f), 7.90531110763549805f);
    float s = x * x;
    float p = fmaf(s, -2.76076847742355e-16f, 2.00018790482477e-13f);
    p = fmaf(p, s, -8.60467152213735e-11f);
    p = fmaf(p, s,  5.12229709037114e-08f);
    p = fmaf(p, s,  1.48572235717979e-05f);
    p = fmaf(p, s,  6.37261928875436e-04f);
    p = fmaf(p, s,  4.89352455891786e-03f);
    p = x * p;
    float q = fmaf(s, 1.19825839466702e-06f, 1.18534705686654e-04f);
    q = fmaf(q, s, 2.26843463243900e-03f);
    q = fmaf(q, s, 4.89352518554385e-03f);
    return p * fast_rcp(q);
}
__device__ __forceinline__ float fast_sigmoid(float x) {
    return fmaf(fast_tanh(0.5f * x), 0.5f, 0.5f);
}

// ---------------- init + converts ----------------
__global__ void init_state_kernel() {
    int i = blockIdx.x * blockDim.x + threadIdx.x;
    if (i == 0) g_bar = 0u;
    if (i < BATCH * HDIM) {
        __nv_bfloat16 z = __float2bfloat16(0.f);
        g_hb_hi[0][i] = z; g_hb_hi[1][i] = z;
        g_hb_lo[0][i] = z; g_hb_lo[1][i] = z;
        g_c[i] = 0.f;
    }
}
__global__ void convert_x_kernel(const float* __restrict__ x) {
    size_t i = (size_t)blockIdx.x * blockDim.x + threadIdx.x;
    if (i >= (size_t)M_TOTAL * IDIM) return;
    float v = x[i];
    __nv_bfloat16 h = __float2bfloat16(v);
    g_x_hi[i] = h;
    g_x_lo[i] = __float2bfloat16(v - __bfloat162float(h));
}
__global__ void convert_wih_kernel(const float* __restrict__ W) {
    size_t i = (size_t)blockIdx.x * blockDim.x + threadIdx.x;
    if (i >= (size_t)G4 * IDIM) return;
    float v = W[i];
    __nv_bfloat16 h = __float2bfloat16(v);
    g_Wih_hi[i] = h;
    g_Wih_lo[i] = __float2bfloat16(v - __bfloat162float(h));
}
// W_hh rearrange for persistent kernel: out_row = blk*32 + g*8 + hl
// maps to in_row = g*1024 + blk*8 + hl  (blk 0..127, g 0..3, hl 0..7)
__global__ void convert_whh_kernel(const float* __restrict__ Whh) {
    size_t idx = (size_t)blockIdx.x * blockDim.x + threadIdx.x;
    if (idx >= (size_t)G4 * HDIM) return;
    int out_row = (int)(idx >> 10);
    int k   = (int)(idx & 1023);
    int blk = out_row >> 5;
    int lg  = out_row & 31;
    int in_row = (lg >> 3) * HDIM + blk * 8 + (lg & 7);
    float v = Whh[(size_t)in_row * HDIM + k];
    __nv_bfloat16 h = __float2bfloat16(v);
    g_Wr_hi[idx] = h;
    g_Wr_lo[idx] = __float2bfloat16(v - __bfloat162float(h));
}

// ---------------- input projection GEMM (split-bf16 HMMA) ----------------
#define GI_STRIDE 40
#define GI_AHI   0
#define GI_ALO   (128*GI_STRIDE*2)
#define GI_BHI   (2*128*GI_STRIDE*2)
#define GI_BLO   (3*128*GI_STRIDE*2)
#define GI_STAGE (4*128*GI_STRIDE*2)
#define GI_SMEM  (3*GI_STAGE)

__global__ void __launch_bounds__(256, 1)
gemm_input_tc(const float* __restrict__ bih, const float* __restrict__ bhh) {
    extern __shared__ char smem[];
    const uint32_t sb = smem_u32(smem);
    const int tid = threadIdx.x, wid = tid >> 5, lane = tid & 31;
    const int mbase = blockIdx.x * 128;
    const int nbase = blockIdx.y * 128;
    const int wm = wid & 1, wn = wid >> 1;

    float acc[4][4][4] = {};

#define GI_ISSUE(i) do {                                                      \
    uint32_t st = sb + ((i) % 3) * GI_STAGE;                                  \
    _Pragma("unroll")                                                         \
    for (int p = 0; p < 2; p++) {                                             \
        int u = tid + p * 256; int r = u >> 2, c = u & 3;                     \
        size_t g = (size_t)(mbase + r) * IDIM + (size_t)(i) * 32 + c * 8;     \
        cp16(st + GI_AHI + r * 80 + c * 16, g_x_hi + g);                      \
        cp16(st + GI_ALO + r * 80 + c * 16, g_x_lo + g);                      \
    }                                                                         \
    _Pragma("unroll")                                                         \
    for (int p = 0; p < 2; p++) {                                             \
        int u = tid + p * 256; int r = u >> 2, c = u & 3;                     \
        size_t g = (size_t)(nbase + r) * IDIM + (size_t)(i) * 32 + c * 8;     \
        cp16(st + GI_BHI + r * 80 + c * 16, g_Wih_hi + g);                    \
        cp16(st + GI_BLO + r * 80 + c * 16, g_Wih_lo + g);                    \
    }                                                                         \
} while (0)

    GI_ISSUE(0); CP_COMMIT();
    GI_ISSUE(1); CP_COMMIT();

    for (int i = 0; i < 32; i++) {
        CP_WAIT1();
        __syncthreads();
        if (i + 2 < 32) GI_ISSUE(i + 2);
        CP_COMMIT();

        uint32_t st = sb + (i % 3) * GI_STAGE;
#pragma unroll
        for (int kk = 0; kk < 2; kk++) {
            const int colb = kk * 16 + ((lane >> 4) << 3);
            uint32_t ah[4][4], al[4][4], bh[2][4], bl[2][4];
#pragma unroll
            for (int mt = 0; mt < 4; mt++) {
                int row = wm * 64 + mt * 16 + (lane & 15);
                uint32_t a = st + GI_AHI + row * 80 + colb * 2;
                ldmx4(ah[mt], a);
                ldmx4(al[mt], a + (GI_ALO - GI_AHI));
            }
#pragma unroll
            for (int bt = 0; bt < 2; bt++) {
                int row = wn * 32 + bt * 16 + (lane & 15);
                uint32_t a = st + GI_BHI + row * 80 + colb * 2;
                ldmx4(bh[bt], a);
                ldmx4(bl[bt], a + (GI_BLO - GI_BHI));
            }
#pragma unroll
            for (int mt = 0; mt < 4; mt++)
#pragma unroll
                for (int nt = 0; nt < 4; nt++) {
                    int bt = nt >> 1, ns = nt & 1;
                    mma16816(acc[mt][nt], ah[mt], bh[bt][ns], bh[bt][ns + 2]);
                    mma16816(acc[mt][nt], ah[mt], bl[bt][ns], bl[bt][ns + 2]);
                    mma16816(acc[mt][nt], al[mt], bh[bt][ns], bh[bt][ns + 2]);
                }
        }
    }

#pragma unroll
    for (int mt = 0; mt < 4; mt++) {
        int m0 = mbase + wm * 64 + mt * 16 + (lane >> 2);
#pragma unroll
        for (int nt = 0; nt < 4; nt++) {
            int n = nbase + wn * 32 + nt * 8 + (lane & 3) * 2;
            float b0 = bih[n] + bhh[n];
            float b1 = bih[n + 1] + bhh[n + 1];
            *(float2*)(g_xg + (size_t)m0 * G4 + n) =
                make_float2(acc[mt][nt][0] + b0, acc[mt][nt][1] + b1);
            *(float2*)(g_xg + (size_t)(m0 + 8) * G4 + n) =
                make_float2(acc[mt][nt][2] + b0, acc[mt][nt][3] + b1);
        }
    }
}

// ---------------- persistent LSTM step kernel ----------------
// Grid 128 (one wave), 512 threads. Block owns 32 W rows = 4 gates x 8 hcols
// (hcols blk*8..blk*8+7). W slice (hi+lo, 144KB) lives in smem for all 512
// steps. Per step: stream h (hi+lo) via 3-stage cp.async, D[32x64] split-bf16
// HMMA, block-local cell update, grid barrier.
//
// smem map (bytes):
//   [0,      73728)  W_hi  [16 chunks][32 rows][72 elems] (144B row stride)
//   [73728, 147456)  W_lo  same layout
//   [147456,202752)  h stages x3: each { hi [64][72], lo [64][72] } = 18432
//   gate exchange overlays stage 1 region (147456+18432)
#define PS_WHI   0
#define PS_WLO   73728
#define PS_HST   147456
#define PS_STAGE 18432
#define PS_SMEM  (PS_HST + 3*PS_STAGE)   // 202752

__global__ void __launch_bounds__(512, 1)
lstm_persistent(float* __restrict__ Hout, float* __restrict__ Cout) {
    extern __shared__ char smem[];
    const uint32_t sb = smem_u32(smem);
    const int tid = threadIdx.x, wid = tid >> 5, lane = tid & 31;
    const int blk = blockIdx.x;
    const int wn = wid & 7;        // n-tile (8 batches)
    const int wm = wid >> 3;       // m-tile (16 rows)

    // ---- preload W slice (hi+lo) into smem: 16 chunks x 32 rows x 64 bf16 ----
#pragma unroll
    for (int p = 0; p < 8; p++) {
        int u = tid + p * 512;
        int ch = u >> 8, r = (u >> 3) & 31, c = u & 7;
        size_t g = (size_t)(blk * 32 + r) * HDIM + ch * 64 + c * 8;
        uint32_t dst = ch * 4608 + r * 144 + c * 16;
        cp16(sb + PS_WHI + dst, g_Wr_hi + g);
        cp16(sb + PS_WLO + dst, g_Wr_lo + g);
    }
    CP_COMMIT();
    CP_WAIT0();
    __syncthreads();

    float* sg = (float*)(smem + PS_HST + PS_STAGE);  // gate exchange [32][68]

    for (int t = 0; t < SEQ; t++) {
        const int pin = t & 1, pout = pin ^ 1;
        const __nv_bfloat16* hhi = g_hb_hi[pin];
        const __nv_bfloat16* hlo = g_hb_lo[pin];

        float acc[2][4] = {};

#define PS_ISSUE(i) do {                                                     \
    uint32_t st = sb + PS_HST + ((i) % 3) * PS_STAGE;                        \
    int r = tid >> 3, c = tid & 7;                                           \
    size_t g = (size_t)r * HDIM + (size_t)(i) * 64 + c * 8;                  \
    cp16(st + r * 144 + c * 16, hhi + g);                                    \
    cp16(st + 9216 + r * 144 + c * 16, hlo + g);                             \
} while (0)

        PS_ISSUE(0); CP_COMMIT();
        PS_ISSUE(1); CP_COMMIT();

        for (int i = 0; i < 16; i++) {
            CP_WAIT1();
            __syncthreads();
            if (i + 2 < 16) PS_ISSUE(i + 2);
            CP_COMMIT();

            uint32_t hstg  = sb + PS_HST + (i % 3) * PS_STAGE;
            uint32_t wbase = sb + i * 4608;
#pragma unroll
            for (int kq = 0; kq < 2; kq++) {
                uint32_t bh[4], bl[4];
                uint32_t baddr = hstg + (wn * 8 + (lane & 7)) * 144
                               + (kq * 32 + (lane >> 3) * 8) * 2;
                ldmx4(bh, baddr);
                ldmx4(bl, baddr + 9216);
#pragma unroll
                for (int ss = 0; ss < 2; ss++) {
                    uint32_t ah[4], al[4];
                    uint32_t aaddr = wbase + PS_WHI
                                   + (wm * 16 + (lane & 15)) * 144
                                   + ((kq * 2 + ss) * 16 + (lane >> 4) * 8) * 2;
                    ldmx4(ah, aaddr);
                    ldmx4(al, aaddr + (PS_WLO - PS_WHI));
                    mma16816(acc[0], ah, bh[ss * 2], bh[ss * 2 + 1]);
                    mma16816(acc[0], ah, bl[ss * 2], bl[ss * 2 + 1]);
                    mma16816(acc[1], al, bh[ss * 2], bh[ss * 2 + 1]);
                }
            }
#pragma unroll
            for (int q = 0; q < 4; q++) acc[0][q] += acc[1][q];
            acc[1][0] = acc[1][1] = acc[1][2] = acc[1][3] = 0.f;
        }

        __syncthreads();  // all stage reads done; reuse stage1 as gate buffer

        // gate exchange: rows = wm*16 + frag rows, cols = batches wn*8..
        {
            int row = wm * 16 + (lane >> 2);
            int col = wn * 8 + (lane & 3) * 2;
            sg[row * 68 + col]           = acc[0][0];
            sg[row * 68 + col + 1]       = acc[0][1];
            sg[(row + 8) * 68 + col]     = acc[0][2];
            sg[(row + 8) * 68 + col + 1] = acc[0][3];
        }
        __syncthreads();

        // cell update: 1 cell/thread: hl = tid&7, b = tid>>3
        {
            const int hl = tid & 7;
            const int b  = tid >> 3;
            const int hcol = blk * 8 + hl;
            size_t xbase = ((size_t)b * SEQ + t) * G4 + hcol;
            float gi = sg[(0 * 8 + hl) * 68 + b] + g_xg[xbase];
            float gf = sg[(1 * 8 + hl) * 68 + b] + g_xg[xbase + 1024];
            float gg = sg[(2 * 8 + hl) * 68 + b] + g_xg[xbase + 2048];
            float go = sg[(3 * 8 + hl) * 68 + b] + g_xg[xbase + 3072];

            float iv = fast_sigmoid(gi);
            float fv = fast_sigmoid(gf);
            float gv = fast_tanh(gg);
            float ov = fast_sigmoid(go);

            float cold = g_c[hcol * BATCH + b];
            float cnew = fv * cold + iv * gv;
            float hnew = ov * fast_tanh(cnew);

            g_c[hcol * BATCH + b] = cnew;

            __nv_bfloat16 hh = __float2bfloat16(hnew);
            g_hb_hi[pout][b * HDIM + hcol] = hh;
            g_hb_lo[pout][b * HDIM + hcol] =
                __float2bfloat16(hnew - __bfloat162float(hh));

            size_t oidx = ((size_t)b * SEQ + t) * HDIM + hcol;
            Hout[oidx] = hnew;
            Cout[oidx] = cnew;
        }

        // grid barrier (skip after last step). All 128 blocks are co-resident.
        if (t < SEQ - 1) {
            __syncthreads();
            __threadfence();
            if (tid == 0) {
                atomicAdd(&g_bar, 1u);
                unsigned target = 128u * (unsigned)(t + 1);
                while (atomicAdd(&g_bar, 0u) < target) {}
            }
            __syncthreads();
        }
    }
}

// ---------------- launch ----------------
extern "C" void kernel_launch(void* const* d_in, const int* in_sizes, int n_in,
                              void* d_out, int out_size) {
    const float* x    = (const float*)d_in[0];
    const float* Wih  = (const float*)d_in[1];
    const float* Whh  = (const float*)d_in[2];
    const float* bih  = (const float*)d_in[3];
    const float* bhh  = (const float*)d_in[4];

    float* Hout = (float*)d_out;
    float* Cout = Hout + (size_t)BATCH * SEQ * HDIM;

    cudaFuncSetAttribute(gemm_input_tc,   cudaFuncAttributeMaxDynamicSharedMemorySize, GI_SMEM);
    cudaFuncSetAttribute(lstm_persistent, cudaFuncAttributeMaxDynamicSharedMemorySize, PS_SMEM);

    init_state_kernel<<<(BATCH * HDIM + 255) / 256, 256>>>();
    convert_x_kernel<<<(int)(((size_t)M_TOTAL * IDIM + 255) / 256), 256>>>(x);
    convert_wih_kernel<<<(int)(((size_t)G4 * IDIM + 255) / 256), 256>>>(Wih);
    convert_whh_kernel<<<(int)(((size_t)G4 * HDIM + 255) / 256), 256>>>(Whh);

    dim3 g1(M_TOTAL / 128, G4 / 128);   // 256 x 32
    gemm_input_tc<<<g1, 256, GI_SMEM>>>(bih, bhh);

    lstm_persistent<<<128, 512, PS_SMEM>>>(Hout, Cout);
}

// round 7
// speedup vs baseline: 6.0236x; 1.0184x over previous
#include <cuda_runtime.h>
#include <cuda_bf16.h>
#include <stdint.h>

#define BATCH 64
#define SEQ   512
#define IDIM  1024
#define HDIM  1024
#define G4    4096
#define M_TOTAL (BATCH*SEQ)

// ---------------- scratch (no cudaMalloc allowed) ----------------
__device__ float g_xg[(size_t)M_TOTAL * G4];
__device__ __align__(16) __nv_bfloat16 g_x_hi[(size_t)M_TOTAL * IDIM];
__device__ __align__(16) __nv_bfloat16 g_x_lo[(size_t)M_TOTAL * IDIM];
__device__ __align__(16) __nv_bfloat16 g_Wih_hi[(size_t)G4 * IDIM];
__device__ __align__(16) __nv_bfloat16 g_Wih_lo[(size_t)G4 * IDIM];
__device__ __align__(16) __nv_bfloat16 g_Wr_hi[(size_t)G4 * HDIM];   // rearranged W_hh
__device__ __align__(16) __nv_bfloat16 g_Wr_lo[(size_t)G4 * HDIM];
__device__ __align__(16) __nv_bfloat16 g_hb_hi[2][BATCH * HDIM];
__device__ __align__(16) __nv_bfloat16 g_hb_lo[2][BATCH * HDIM];
__device__ unsigned g_bar;

// ---------------- PTX helpers (base compute_103-safe) ----------------
__device__ __forceinline__ uint32_t smem_u32(const void* p) {
    return (uint32_t)__cvta_generic_to_shared(p);
}
__device__ __forceinline__ void ldmx4(uint32_t r[4], uint32_t addr) {
    asm volatile("ldmatrix.sync.aligned.m8n8.x4.shared.b16 {%0,%1,%2,%3}, [%4];"
        : "=r"(r[0]), "=r"(r[1]), "=r"(r[2]), "=r"(r[3]) : "r"(addr));
}
__device__ __forceinline__ void mma16816(float c[4], const uint32_t a[4],
                                         uint32_t b0, uint32_t b1) {
    asm volatile("mma.sync.aligned.m16n8k16.row.col.f32.bf16.bf16.f32 "
        "{%0,%1,%2,%3}, {%4,%5,%6,%7}, {%8,%9}, {%0,%1,%2,%3};"
        : "+f"(c[0]), "+f"(c[1]), "+f"(c[2]), "+f"(c[3])
        : "r"(a[0]), "r"(a[1]), "r"(a[2]), "r"(a[3]), "r"(b0), "r"(b1));
}
__device__ __forceinline__ void cp16(uint32_t dst, const void* src) {
    asm volatile("cp.async.cg.shared.global [%0], [%1], 16;" :: "r"(dst), "l"(src));
}
#define CP_COMMIT() asm volatile("cp.async.commit_group;" ::: "memory")
#define CP_WAIT1()  asm volatile("cp.async.wait_group 1;" ::: "memory")
#define CP_WAIT0()  asm volatile("cp.async.wait_group 0;" ::: "memory")

__device__ __forceinline__ unsigned ld_acq(const unsigned* p) {
    unsigned v;
    asm volatile("ld.acquire.gpu.u32 %0, [%1];" : "=r"(v) : "l"(p) : "memory");
    return v;
}

// ---------------- MUFU-free activations ----------------
__device__ __forceinline__ float fast_rcp(float q) {
    float r = __uint_as_float(0x7EF311C2u - __float_as_uint(q));
    r = r * (2.0f - q * r);
    r = r * (2.0f - q * r);
    r = r * (2.0f - q * r);
    return r;
}
__device__ __forceinline__ float fast_tanh(float x) {
    x = fminf(fmaxf(x, -7.90531110763549805f), 7.90531110763549805f);
    float s = x * x;
    float p = fmaf(s, -2.76076847742355e-16f, 2.00018790482477e-13f);
    p = fmaf(p, s, -8.60467152213735e-11f);
    p = fmaf(p, s,  5.12229709037114e-08f);
    p = fmaf(p, s,  1.48572235717979e-05f);
    p = fmaf(p, s,  6.37261928875436e-04f);
    p = fmaf(p, s,  4.89352455891786e-03f);
    p = x * p;
    float q = fmaf(s, 1.19825839466702e-06f, 1.18534705686654e-04f);
    q = fmaf(q, s, 2.26843463243900e-03f);
    q = fmaf(q, s, 4.89352518554385e-03f);
    return p * fast_rcp(q);
}
__device__ __forceinline__ float fast_sigmoid(float x) {
    return fmaf(fast_tanh(0.5f * x), 0.5f, 0.5f);
}

// ---------------- init + converts ----------------
__global__ void init_state_kernel() {
    int i = blockIdx.x * blockDim.x + threadIdx.x;
    if (i == 0) g_bar = 0u;
    if (i < BATCH * HDIM) {
        __nv_bfloat16 z = __float2bfloat16(0.f);
        g_hb_hi[0][i] = z; g_hb_hi[1][i] = z;
        g_hb_lo[0][i] = z; g_hb_lo[1][i] = z;
    }
}
__global__ void convert_x_kernel(const float* __restrict__ x) {
    size_t i = (size_t)blockIdx.x * blockDim.x + threadIdx.x;
    if (i >= (size_t)M_TOTAL * IDIM) return;
    float v = x[i];
    __nv_bfloat16 h = __float2bfloat16(v);
    g_x_hi[i] = h;
    g_x_lo[i] = __float2bfloat16(v - __bfloat162float(h));
}
__global__ void convert_wih_kernel(const float* __restrict__ W) {
    size_t i = (size_t)blockIdx.x * blockDim.x + threadIdx.x;
    if (i >= (size_t)G4 * IDIM) return;
    float v = W[i];
    __nv_bfloat16 h = __float2bfloat16(v);
    g_Wih_hi[i] = h;
    g_Wih_lo[i] = __float2bfloat16(v - __bfloat162float(h));
}
// W_hh rearrange: out_row = blk*32 + g*8 + hl  <-  in_row = g*1024 + blk*8 + hl
__global__ void convert_whh_kernel(const float* __restrict__ Whh) {
    size_t idx = (size_t)blockIdx.x * blockDim.x + threadIdx.x;
    if (idx >= (size_t)G4 * HDIM) return;
    int out_row = (int)(idx >> 10);
    int k   = (int)(idx & 1023);
    int blk = out_row >> 5;
    int lg  = out_row & 31;
    int in_row = (lg >> 3) * HDIM + blk * 8 + (lg & 7);
    float v = Whh[(size_t)in_row * HDIM + k];
    __nv_bfloat16 h = __float2bfloat16(v);
    g_Wr_hi[idx] = h;
    g_Wr_lo[idx] = __float2bfloat16(v - __bfloat162float(h));
}

// ---------------- input projection GEMM (split-bf16 HMMA) ----------------
#define GI_STRIDE 40
#define GI_AHI   0
#define GI_ALO   (128*GI_STRIDE*2)
#define GI_BHI   (2*128*GI_STRIDE*2)
#define GI_BLO   (3*128*GI_STRIDE*2)
#define GI_STAGE (4*128*GI_STRIDE*2)
#define GI_SMEM  (3*GI_STAGE)

__global__ void __launch_bounds__(256, 1)
gemm_input_tc(const float* __restrict__ bih, const float* __restrict__ bhh) {
    extern __shared__ char smem[];
    const uint32_t sb = smem_u32(smem);
    const int tid = threadIdx.x, wid = tid >> 5, lane = tid & 31;
    const int mbase = blockIdx.x * 128;
    const int nbase = blockIdx.y * 128;
    const int wm = wid & 1, wn = wid >> 1;

    float acc[4][4][4] = {};

#define GI_ISSUE(i) do {                                                      \
    uint32_t st = sb + ((i) % 3) * GI_STAGE;                                  \
    _Pragma("unroll")                                                         \
    for (int p = 0; p < 2; p++) {                                             \
        int u = tid + p * 256; int r = u >> 2, c = u & 3;                     \
        size_t g = (size_t)(mbase + r) * IDIM + (size_t)(i) * 32 + c * 8;     \
        cp16(st + GI_AHI + r * 80 + c * 16, g_x_hi + g);                      \
        cp16(st + GI_ALO + r * 80 + c * 16, g_x_lo + g);                      \
    }                                                                         \
    _Pragma("unroll")                                                         \
    for (int p = 0; p < 2; p++) {                                             \
        int u = tid + p * 256; int r = u >> 2, c = u & 3;                     \
        size_t g = (size_t)(nbase + r) * IDIM + (size_t)(i) * 32 + c * 8;     \
        cp16(st + GI_BHI + r * 80 + c * 16, g_Wih_hi + g);                    \
        cp16(st + GI_BLO + r * 80 + c * 16, g_Wih_lo + g);                    \
    }                                                                         \
} while (0)

    GI_ISSUE(0); CP_COMMIT();
    GI_ISSUE(1); CP_COMMIT();

    for (int i = 0; i < 32; i++) {
        CP_WAIT1();
        __syncthreads();           // chunk i visible to all; all done with buf (i+2)%3
        if (i + 2 < 32) GI_ISSUE(i + 2);
        CP_COMMIT();

        uint32_t st = sb + (i % 3) * GI_STAGE;
#pragma unroll
        for (int kk = 0; kk < 2; kk++) {
            const int colb = kk * 16 + ((lane >> 4) << 3);
            uint32_t ah[4][4], al[4][4], bh[2][4], bl[2][4];
#pragma unroll
            for (int mt = 0; mt < 4; mt++) {
                int row = wm * 64 + mt * 16 + (lane & 15);
                uint32_t a = st + GI_AHI + row * 80 + colb * 2;
                ldmx4(ah[mt], a);
                ldmx4(al[mt], a + (GI_ALO - GI_AHI));
            }
#pragma unroll
            for (int bt = 0; bt < 2; bt++) {
                int row = wn * 32 + bt * 16 + (lane & 15);
                uint32_t a = st + GI_BHI + row * 80 + colb * 2;
                ldmx4(bh[bt], a);
                ldmx4(bl[bt], a + (GI_BLO - GI_BHI));
            }
#pragma unroll
            for (int mt = 0; mt < 4; mt++)
#pragma unroll
                for (int nt = 0; nt < 4; nt++) {
                    int bt = nt >> 1, ns = nt & 1;
                    mma16816(acc[mt][nt], ah[mt], bh[bt][ns], bh[bt][ns + 2]);
                    mma16816(acc[mt][nt], ah[mt], bl[bt][ns], bl[bt][ns + 2]);
                    mma16816(acc[mt][nt], al[mt], bh[bt][ns], bh[bt][ns + 2]);
                }
        }
    }

#pragma unroll
    for (int mt = 0; mt < 4; mt++) {
        int m0 = mbase + wm * 64 + mt * 16 + (lane >> 2);
#pragma unroll
        for (int nt = 0; nt < 4; nt++) {
            int n = nbase + wn * 32 + nt * 8 + (lane & 3) * 2;
            float b0 = bih[n] + bhh[n];
            float b1 = bih[n + 1] + bhh[n + 1];
            __stcs((float2*)(g_xg + (size_t)m0 * G4 + n),
                   make_float2(acc[mt][nt][0] + b0, acc[mt][nt][1] + b1));
            __stcs((float2*)(g_xg + (size_t)(m0 + 8) * G4 + n),
                   make_float2(acc[mt][nt][2] + b0, acc[mt][nt][3] + b1));
        }
    }
}

// ---------------- persistent LSTM step kernel ----------------
#define PS_WHI   0
#define PS_WLO   73728
#define PS_HST   147456
#define PS_STAGE 18432
#define PS_SMEM  (PS_HST + 3*PS_STAGE)   // 202752

__global__ void __launch_bounds__(512, 1)
lstm_persistent(float* __restrict__ Hout, float* __restrict__ Cout) {
    extern __shared__ char smem[];
    const uint32_t sb = smem_u32(smem);
    const int tid = threadIdx.x, wid = tid >> 5, lane = tid & 31;
    const int blk = blockIdx.x;
    const int wn = wid & 7;        // n-tile (8 batches)
    const int wm = wid >> 3;       // m-tile (16 rows)

    // ---- preload W slice (hi+lo): 16 chunks x 32 rows x 64 bf16 each ----
#pragma unroll
    for (int p = 0; p < 8; p++) {
        int u = tid + p * 512;
        int ch = u >> 8, r = (u >> 3) & 31, c = u & 7;
        size_t g = (size_t)(blk * 32 + r) * HDIM + ch * 64 + c * 8;
        uint32_t dst = ch * 4608 + r * 144 + c * 16;
        cp16(sb + PS_WHI + dst, g_Wr_hi + g);
        cp16(sb + PS_WLO + dst, g_Wr_lo + g);
    }
    CP_COMMIT();
    CP_WAIT0();
    __syncthreads();

    float* sg = (float*)(smem + PS_HST);   // gate exchange [32][68] (overlays stage 0)

    // static cell ownership: c lives in a register for all 512 steps
    const int hl = tid & 7;
    const int bcell = tid >> 3;
    const int hcol = blk * 8 + hl;
    float creg = 0.f;

    // xg prefetch registers (for step t)
    float xgi, xgf, xgg, xgo;
    {
        size_t xb = ((size_t)bcell * SEQ + 0) * G4 + hcol;
        xgi = __ldcs(g_xg + xb);
        xgf = __ldcs(g_xg + xb + 1024);
        xgg = __ldcs(g_xg + xb + 2048);
        xgo = __ldcs(g_xg + xb + 3072);
    }

    for (int t = 0; t < SEQ; t++) {
        const int pin = t & 1, pout = pin ^ 1;
        const __nv_bfloat16* hhi = g_hb_hi[pin];
        const __nv_bfloat16* hlo = g_hb_lo[pin];

        float acc[2][4] = {};

#define PS_ISSUE(i) do {                                                     \
    uint32_t st = sb + PS_HST + ((i) % 3) * PS_STAGE;                        \
    int r = tid >> 3, c = tid & 7;                                           \
    size_t g = (size_t)r * HDIM + (size_t)(i) * 64 + c * 8;                  \
    cp16(st + r * 144 + c * 16, hhi + g);                                    \
    cp16(st + 9216 + r * 144 + c * 16, hlo + g);                             \
} while (0)

        PS_ISSUE(0); CP_COMMIT();
        PS_ISSUE(1); CP_COMMIT();

        for (int i = 0; i < 16; i++) {
            CP_WAIT1();
            __syncthreads();       // chunk i ready; all warps done with buf (i+2)%3
            if (i + 2 < 16) PS_ISSUE(i + 2);
            CP_COMMIT();

            uint32_t hstg  = sb + PS_HST + (i % 3) * PS_STAGE;
            uint32_t wbase = sb + i * 4608;
#pragma unroll
            for (int kq = 0; kq < 2; kq++) {
                uint32_t bh[4], bl[4];
                uint32_t baddr = hstg + (wn * 8 + (lane & 7)) * 144
                               + (kq * 32 + (lane >> 3) * 8) * 2;
                ldmx4(bh, baddr);
                ldmx4(bl, baddr + 9216);
#pragma unroll
                for (int ss = 0; ss < 2; ss++) {
                    uint32_t ah[4], al[4];
                    uint32_t aaddr = wbase + PS_WHI
                                   + (wm * 16 + (lane & 15)) * 144
                                   + ((kq * 2 + ss) * 16 + (lane >> 4) * 8) * 2;
                    ldmx4(ah, aaddr);
                    ldmx4(al, aaddr + (PS_WLO - PS_WHI));
                    mma16816(acc[0], ah, bh[ss * 2], bh[ss * 2 + 1]);
                    mma16816(acc[0], ah, bl[ss * 2], bl[ss * 2 + 1]);
                    mma16816(acc[1], al, bh[ss * 2], bh[ss * 2 + 1]);
                }
            }
        }
#pragma unroll
        for (int q = 0; q < 4; q++) acc[0][q] += acc[1][q];

        __syncthreads();           // all stage reads done; stage 0 reused as sg

        {
            int row = wm * 16 + (lane >> 2);
            int col = wn * 8 + (lane & 3) * 2;
            sg[row * 68 + col]           = acc[0][0];
            sg[row * 68 + col + 1]       = acc[0][1];
            sg[(row + 8) * 68 + col]     = acc[0][2];
            sg[(row + 8) * 68 + col + 1] = acc[0][3];
        }
        __syncthreads();

        // cell update (1 cell/thread, c in register)
        {
            float gi = sg[(0 * 8 + hl) * 68 + bcell] + xgi;
            float gf = sg[(1 * 8 + hl) * 68 + bcell] + xgf;
            float gg = sg[(2 * 8 + hl) * 68 + bcell] + xgg;
            float go = sg[(3 * 8 + hl) * 68 + bcell] + xgo;

            float iv = fast_sigmoid(gi);
            float fv = fast_sigmoid(gf);
            float gv = fast_tanh(gg);
            float ov = fast_sigmoid(go);

            float cnew = fv * creg + iv * gv;
            float hnew = ov * fast_tanh(cnew);
            creg = cnew;

            __nv_bfloat16 hh = __float2bfloat16(hnew);
            g_hb_hi[pout][bcell * HDIM + hcol] = hh;
            g_hb_lo[pout][bcell * HDIM + hcol] =
                __float2bfloat16(hnew - __bfloat162float(hh));

            size_t oidx = ((size_t)bcell * SEQ + t) * HDIM + hcol;
            __stcs(Hout + oidx, hnew);
            __stcs(Cout + oidx, cnew);
        }

        // prefetch next step's xg before the barrier (overlaps spin)
        if (t + 1 < SEQ) {
            size_t xb = ((size_t)bcell * SEQ + (t + 1)) * G4 + hcol;
            xgi = __ldcs(g_xg + xb);
            xgf = __ldcs(g_xg + xb + 1024);
            xgg = __ldcs(g_xg + xb + 2048);
            xgo = __ldcs(g_xg + xb + 3072);

            // grid barrier: release arrive, acquire spin. 128 blocks, one wave.
            __syncthreads();
            if (tid == 0) {
                __threadfence();
                atomicAdd(&g_bar, 1u);
                unsigned target = 128u * (unsigned)(t + 1);
                while (ld_acq(&g_bar) < target) __nanosleep(32);
            }
            __syncthreads();
        }
    }
}

// ---------------- launch ----------------
extern "C" void kernel_launch(void* const* d_in, const int* in_sizes, int n_in,
                              void* d_out, int out_size) {
    const float* x    = (const float*)d_in[0];
    const float* Wih  = (const float*)d_in[1];
    const float* Whh  = (const float*)d_in[2];
    const float* bih  = (const float*)d_in[3];
    const float* bhh  = (const float*)d_in[4];

    float* Hout = (float*)d_out;
    float* Cout = Hout + (size_t)BATCH * SEQ * HDIM;

    cudaFuncSetAttribute(gemm_input_tc,   cudaFuncAttributeMaxDynamicSharedMemorySize, GI_SMEM);
    cudaFuncSetAttribute(lstm_persistent, cudaFuncAttributeMaxDynamicSharedMemorySize, PS_SMEM);

    init_state_kernel<<<(BATCH * HDIM + 255) / 256, 256>>>();
    convert_x_kernel<<<(int)(((size_t)M_TOTAL * IDIM + 255) / 256), 256>>>(x);
    convert_wih_kernel<<<(int)(((size_t)G4 * IDIM + 255) / 256), 256>>>(Wih);
    convert_whh_kernel<<<(int)(((size_t)G4 * HDIM + 255) / 256), 256>>>(Whh);

    dim3 g1(M_TOTAL / 128, G4 / 128);   // 256 x 32
    gemm_input_tc<<<g1, 256, GI_SMEM>>>(bih, bhh);

    lstm_persistent<<<128, 512, PS_SMEM>>>(Hout, Cout);
}

// round 8
// speedup vs baseline: 7.2729x; 1.2074x over previous
#include <cuda_runtime.h>
#include <cuda_bf16.h>
#include <cuda_fp16.h>
#include <stdint.h>

#define BATCH 64
#define SEQ   512
#define IDIM  1024
#define HDIM  1024
#define G4    4096
#define M_TOTAL (BATCH*SEQ)

// ---------------- scratch (no cudaMalloc allowed) ----------------
__device__ float g_xg[(size_t)M_TOTAL * G4];
__device__ __align__(16) __nv_bfloat16 g_x_hi[(size_t)M_TOTAL * IDIM];
__device__ __align__(16) __nv_bfloat16 g_x_lo[(size_t)M_TOTAL * IDIM];
__device__ __align__(16) __nv_bfloat16 g_Wih_hi[(size_t)G4 * IDIM];
__device__ __align__(16) __nv_bfloat16 g_Wih_lo[(size_t)G4 * IDIM];
__device__ __align__(16) __half g_Wf[(size_t)G4 * HDIM];       // rearranged W_hh, fp16
__device__ __align__(16) __half g_hh[2][BATCH * HDIM];         // h state fp16 hi
__device__ __align__(16) __half g_hl[2][BATCH * HDIM];         // h state fp16 lo
__device__ unsigned g_bar;

// ---------------- PTX helpers (base compute_103-safe) ----------------
__device__ __forceinline__ uint32_t smem_u32(const void* p) {
    return (uint32_t)__cvta_generic_to_shared(p);
}
__device__ __forceinline__ void ldmx4(uint32_t r[4], uint32_t addr) {
    asm volatile("ldmatrix.sync.aligned.m8n8.x4.shared.b16 {%0,%1,%2,%3}, [%4];"
        : "=r"(r[0]), "=r"(r[1]), "=r"(r[2]), "=r"(r[3]) : "r"(addr));
}
__device__ __forceinline__ void mma_bf16(float c[4], const uint32_t a[4],
                                         uint32_t b0, uint32_t b1) {
    asm volatile("mma.sync.aligned.m16n8k16.row.col.f32.bf16.bf16.f32 "
        "{%0,%1,%2,%3}, {%4,%5,%6,%7}, {%8,%9}, {%0,%1,%2,%3};"
        : "+f"(c[0]), "+f"(c[1]), "+f"(c[2]), "+f"(c[3])
        : "r"(a[0]), "r"(a[1]), "r"(a[2]), "r"(a[3]), "r"(b0), "r"(b1));
}
__device__ __forceinline__ void mma_f16(float c[4], const uint32_t a[4],
                                        uint32_t b0, uint32_t b1) {
    asm volatile("mma.sync.aligned.m16n8k16.row.col.f32.f16.f16.f32 "
        "{%0,%1,%2,%3}, {%4,%5,%6,%7}, {%8,%9}, {%0,%1,%2,%3};"
        : "+f"(c[0]), "+f"(c[1]), "+f"(c[2]), "+f"(c[3])
        : "r"(a[0]), "r"(a[1]), "r"(a[2]), "r"(a[3]), "r"(b0), "r"(b1));
}
__device__ __forceinline__ void cp16(uint32_t dst, const void* src) {
    asm volatile("cp.async.cg.shared.global [%0], [%1], 16;" :: "r"(dst), "l"(src));
}
#define CP_COMMIT() asm volatile("cp.async.commit_group;" ::: "memory")
#define CP_WAIT1()  asm volatile("cp.async.wait_group 1;" ::: "memory")
#define CP_WAIT0()  asm volatile("cp.async.wait_group 0;" ::: "memory")

__device__ __forceinline__ unsigned ld_acq(const unsigned* p) {
    unsigned v;
    asm volatile("ld.acquire.gpu.u32 %0, [%1];" : "=r"(v) : "l"(p) : "memory");
    return v;
}

// ---------------- MUFU-free activations ----------------
__device__ __forceinline__ float fast_rcp(float q) {
    float r = __uint_as_float(0x7EF311C2u - __float_as_uint(q));
    r = r * (2.0f - q * r);
    r = r * (2.0f - q * r);
    r = r * (2.0f - q * r);
    return r;
}
__device__ __forceinline__ float fast_tanh(float x) {
    x = fminf(fmaxf(x, -7.90531110763549805f), 7.90531110763549805f);
    float s = x * x;
    float p = fmaf(s, -2.76076847742355e-16f, 2.00018790482477e-13f);
    p = fmaf(p, s, -8.60467152213735e-11f);
    p = fmaf(p, s,  5.12229709037114e-08f);
    p = fmaf(p, s,  1.48572235717979e-05f);
    p = fmaf(p, s,  6.37261928875436e-04f);
    p = fmaf(p, s,  4.89352455891786e-03f);
    p = x * p;
    float q = fmaf(s, 1.19825839466702e-06f, 1.18534705686654e-04f);
    q = fmaf(q, s, 2.26843463243900e-03f);
    q = fmaf(q, s, 4.89352518554385e-03f);
    return p * fast_rcp(q);
}
__device__ __forceinline__ float fast_sigmoid(float x) {
    return fmaf(fast_tanh(0.5f * x), 0.5f, 0.5f);
}

// ---------------- init + converts ----------------
__global__ void init_state_kernel() {
    int i = blockIdx.x * blockDim.x + threadIdx.x;
    if (i == 0) g_bar = 0u;
    if (i < BATCH * HDIM) {
        __half z = __float2half(0.f);
        g_hh[0][i] = z; g_hh[1][i] = z;
        g_hl[0][i] = z; g_hl[1][i] = z;
    }
}
__global__ void convert_x_kernel(const float* __restrict__ x) {
    size_t i = (size_t)blockIdx.x * blockDim.x + threadIdx.x;
    if (i >= (size_t)M_TOTAL * IDIM) return;
    float v = x[i];
    __nv_bfloat16 h = __float2bfloat16(v);
    g_x_hi[i] = h;
    g_x_lo[i] = __float2bfloat16(v - __bfloat162float(h));
}
__global__ void convert_wih_kernel(const float* __restrict__ W) {
    size_t i = (size_t)blockIdx.x * blockDim.x + threadIdx.x;
    if (i >= (size_t)G4 * IDIM) return;
    float v = W[i];
    __nv_bfloat16 h = __float2bfloat16(v);
    g_Wih_hi[i] = h;
    g_Wih_lo[i] = __float2bfloat16(v - __bfloat162float(h));
}
// W_hh rearrange (fp16): out_row = blk*32 + g*8 + hl  <-  in_row = g*1024 + blk*8 + hl
__global__ void convert_whh_kernel(const float* __restrict__ Whh) {
    size_t idx = (size_t)blockIdx.x * blockDim.x + threadIdx.x;
    if (idx >= (size_t)G4 * HDIM) return;
    int out_row = (int)(idx >> 10);
    int k   = (int)(idx & 1023);
    int blk = out_row >> 5;
    int lg  = out_row & 31;
    int in_row = (lg >> 3) * HDIM + blk * 8 + (lg & 7);
    g_Wf[idx] = __float2half(Whh[(size_t)in_row * HDIM + k]);
}

// ---------------- input projection GEMM (split-bf16 HMMA, unchanged) -------
#define GI_STRIDE 40
#define GI_AHI   0
#define GI_ALO   (128*GI_STRIDE*2)
#define GI_BHI   (2*128*GI_STRIDE*2)
#define GI_BLO   (3*128*GI_STRIDE*2)
#define GI_STAGE (4*128*GI_STRIDE*2)
#define GI_SMEM  (3*GI_STAGE)

__global__ void __launch_bounds__(256, 1)
gemm_input_tc(const float* __restrict__ bih, const float* __restrict__ bhh) {
    extern __shared__ char smem[];
    const uint32_t sb = smem_u32(smem);
    const int tid = threadIdx.x, wid = tid >> 5, lane = tid & 31;
    const int mbase = blockIdx.x * 128;
    const int nbase = blockIdx.y * 128;
    const int wm = wid & 1, wn = wid >> 1;

    float acc[4][4][4] = {};

#define GI_ISSUE(i) do {                                                      \
    uint32_t st = sb + ((i) % 3) * GI_STAGE;                                  \
    _Pragma("unroll")                                                         \
    for (int p = 0; p < 2; p++) {                                             \
        int u = tid + p * 256; int r = u >> 2, c = u & 3;                     \
        size_t g = (size_t)(mbase + r) * IDIM + (size_t)(i) * 32 + c * 8;     \
        cp16(st + GI_AHI + r * 80 + c * 16, g_x_hi + g);                      \
        cp16(st + GI_ALO + r * 80 + c * 16, g_x_lo + g);                      \
    }                                                                         \
    _Pragma("unroll")                                                         \
    for (int p = 0; p < 2; p++) {                                             \
        int u = tid + p * 256; int r = u >> 2, c = u & 3;                     \
        size_t g = (size_t)(nbase + r) * IDIM + (size_t)(i) * 32 + c * 8;     \
        cp16(st + GI_BHI + r * 80 + c * 16, g_Wih_hi + g);                    \
        cp16(st + GI_BLO + r * 80 + c * 16, g_Wih_lo + g);                    \
    }                                                                         \
} while (0)

    GI_ISSUE(0); CP_COMMIT();
    GI_ISSUE(1); CP_COMMIT();

    for (int i = 0; i < 32; i++) {
        CP_WAIT1();
        __syncthreads();
        if (i + 2 < 32) GI_ISSUE(i + 2);
        CP_COMMIT();

        uint32_t st = sb + (i % 3) * GI_STAGE;
#pragma unroll
        for (int kk = 0; kk < 2; kk++) {
            const int colb = kk * 16 + ((lane >> 4) << 3);
            uint32_t ah[4][4], al[4][4], bh[2][4], bl[2][4];
#pragma unroll
            for (int mt = 0; mt < 4; mt++) {
                int row = wm * 64 + mt * 16 + (lane & 15);
                uint32_t a = st + GI_AHI + row * 80 + colb * 2;
                ldmx4(ah[mt], a);
                ldmx4(al[mt], a + (GI_ALO - GI_AHI));
            }
#pragma unroll
            for (int bt = 0; bt < 2; bt++) {
                int row = wn * 32 + bt * 16 + (lane & 15);
                uint32_t a = st + GI_BHI + row * 80 + colb * 2;
                ldmx4(bh[bt], a);
                ldmx4(bl[bt], a + (GI_BLO - GI_BHI));
            }
#pragma unroll
            for (int mt = 0; mt < 4; mt++)
#pragma unroll
                for (int nt = 0; nt < 4; nt++) {
                    int bt = nt >> 1, ns = nt & 1;
                    mma_bf16(acc[mt][nt], ah[mt], bh[bt][ns], bh[bt][ns + 2]);
                    mma_bf16(acc[mt][nt], ah[mt], bl[bt][ns], bl[bt][ns + 2]);
                    mma_bf16(acc[mt][nt], al[mt], bh[bt][ns], bh[bt][ns + 2]);
                }
        }
    }

#pragma unroll
    for (int mt = 0; mt < 4; mt++) {
        int m0 = mbase + wm * 64 + mt * 16 + (lane >> 2);
#pragma unroll
        for (int nt = 0; nt < 4; nt++) {
            int n = nbase + wn * 32 + nt * 8 + (lane & 3) * 2;
            float b0 = bih[n] + bhh[n];
            float b1 = bih[n + 1] + bhh[n + 1];
            __stcs((float2*)(g_xg + (size_t)m0 * G4 + n),
                   make_float2(acc[mt][nt][0] + b0, acc[mt][nt][1] + b1));
            __stcs((float2*)(g_xg + (size_t)(m0 + 8) * G4 + n),
                   make_float2(acc[mt][nt][2] + b0, acc[mt][nt][3] + b1));
        }
    }
}

// ---------------- persistent LSTM step kernel (fp16 2-combo) ----------------
// Grid 128, 512 threads. Block owns 32 W rows (4 gates x 8 hcols).
// W fp16 slice (69.6KB) resident in smem; per step: 8 chunks of K=128,
// h hi/lo fp16 streamed 3-stage. Warps: wm(2) x wn(4) x kw(2); warp tile
// M16 x N16 x K64(half-chunk). Partial sums over kw combined via smem.
// Row stride 272B (17x16B): 8-row LDSM phases hit banks 4r%32 -> conflict-free.
#define PS_W      0
#define PS_WCH    8704                   // 32 rows * 272B per chunk
#define PS_H      69632                  // 8 * PS_WCH
#define PS_HSTAGE 34816                  // hi 17408 + lo 17408
#define PS_SMEM   (PS_H + 3*PS_HSTAGE)   // 174080

__global__ void __launch_bounds__(512, 1)
lstm_persistent(float* __restrict__ Hout, float* __restrict__ Cout) {
    extern __shared__ char smem[];
    const uint32_t sb = smem_u32(smem);
    const int tid = threadIdx.x, wid = tid >> 5, lane = tid & 31;
    const int blk = blockIdx.x;
    const int wm = wid & 1;            // M half (16 rows)
    const int wn = (wid >> 1) & 3;     // N quarter (16 batches)
    const int kw = wid >> 3;           // K half within chunk (64)

    // ---- preload W slice fp16: 8 chunks x 32 rows x 128 k ----
#pragma unroll
    for (int p = 0; p < 8; p++) {
        int u = tid + p * 512;
        int ch = u >> 9, r = (u >> 4) & 31, c = u & 15;
        size_t g = (size_t)(blk * 32 + r) * HDIM + ch * 128 + c * 8;
        cp16(sb + PS_W + ch * PS_WCH + r * 272 + c * 16, g_Wf + g);
    }
    CP_COMMIT();
    CP_WAIT0();
    __syncthreads();

    float* sg = (float*)(smem + PS_H);   // [2 kw][32 rows][68] overlays stage 0

    const int hl = tid & 7;
    const int bcell = tid >> 3;
    const int hcol = blk * 8 + hl;
    float creg = 0.f;

    float xgi, xgf, xgg, xgo;
    {
        size_t xb = ((size_t)bcell * SEQ + 0) * G4 + hcol;
        xgi = __ldcs(g_xg + xb);
        xgf = __ldcs(g_xg + xb + 1024);
        xgg = __ldcs(g_xg + xb + 2048);
        xgo = __ldcs(g_xg + xb + 3072);
    }

    for (int t = 0; t < SEQ; t++) {
        const int pin = t & 1, pout = pin ^ 1;
        const __half* hhp = g_hh[pin];
        const __half* hlp = g_hl[pin];

        float accH[2][4] = {};   // [n-half] W*h_hi
        float accL[2][4] = {};   // [n-half] W*h_lo

#define PS_ISSUE(i) do {                                                     \
    uint32_t st = sb + PS_H + ((i) % 3) * PS_HSTAGE;                         \
    _Pragma("unroll")                                                        \
    for (int p = 0; p < 2; p++) {                                            \
        int u = tid + p * 512; int r = u >> 4, c = u & 15;                   \
        size_t g = (size_t)r * HDIM + (size_t)(i) * 128 + c * 8;             \
        cp16(st + r * 272 + c * 16, hhp + g);                                \
        cp16(st + 17408 + r * 272 + c * 16, hlp + g);                        \
    }                                                                        \
} while (0)

        PS_ISSUE(0); CP_COMMIT();
        PS_ISSUE(1); CP_COMMIT();

        for (int i = 0; i < 8; i++) {
            CP_WAIT1();
            __syncthreads();
            if (i + 2 < 8) PS_ISSUE(i + 2);
            CP_COMMIT();

            uint32_t hstg  = sb + PS_H + (i % 3) * PS_HSTAGE;
            uint32_t wbase = sb + PS_W + i * PS_WCH;

            // B fragments: n16 x k64(this kw) hi+lo
            uint32_t bh[2][2][4], bl[2][2][4];   // [nh][k32]
#pragma unroll
            for (int nh = 0; nh < 2; nh++)
#pragma unroll
                for (int k32 = 0; k32 < 2; k32++) {
                    uint32_t a = hstg + (wn * 16 + nh * 8 + (lane & 7)) * 272
                               + (kw * 64 + k32 * 32 + (lane >> 3) * 8) * 2;
                    ldmx4(bh[nh][k32], a);
                    ldmx4(bl[nh][k32], a + 17408);
                }
#pragma unroll
            for (int ks = 0; ks < 4; ks++) {
                uint32_t a[4];
                ldmx4(a, wbase + (wm * 16 + (lane & 15)) * 272
                         + (kw * 64 + ks * 16 + (lane >> 4) * 8) * 2);
                int k32 = ks >> 1, pi = (ks & 1) * 2;
#pragma unroll
                for (int nh = 0; nh < 2; nh++) {
                    mma_f16(accH[nh], a, bh[nh][k32][pi], bh[nh][k32][pi + 1]);
                    mma_f16(accL[nh], a, bl[nh][k32][pi], bl[nh][k32][pi + 1]);
                }
            }
        }
#pragma unroll
        for (int nh = 0; nh < 2; nh++)
#pragma unroll
            for (int q = 0; q < 4; q++) accH[nh][q] += accL[nh][q];

        __syncthreads();           // all stage reads done; stage 0 reused as sg

        // gate exchange: sg[kw][row 0..31][batch 0..63]
        {
            int row = wm * 16 + (lane >> 2);
            float* base = sg + kw * 2176;
#pragma unroll
            for (int nh = 0; nh < 2; nh++) {
                int col = wn * 16 + nh * 8 + (lane & 3) * 2;
                base[row * 68 + col]           = accH[nh][0];
                base[row * 68 + col + 1]       = accH[nh][1];
                base[(row + 8) * 68 + col]     = accH[nh][2];
                base[(row + 8) * 68 + col + 1] = accH[nh][3];
            }
        }
        __syncthreads();

        // cell update (1 cell/thread, c in register); sum the two kw halves
        {
            float gi = sg[(0 * 8 + hl) * 68 + bcell] + sg[2176 + (0 * 8 + hl) * 68 + bcell] + xgi;
            float gf = sg[(1 * 8 + hl) * 68 + bcell] + sg[2176 + (1 * 8 + hl) * 68 + bcell] + xgf;
            float gg = sg[(2 * 8 + hl) * 68 + bcell] + sg[2176 + (2 * 8 + hl) * 68 + bcell] + xgg;
            float go = sg[(3 * 8 + hl) * 68 + bcell] + sg[2176 + (3 * 8 + hl) * 68 + bcell] + xgo;

            float iv = fast_sigmoid(gi);
            float fv = fast_sigmoid(gf);
            float gv = fast_tanh(gg);
            float ov = fast_sigmoid(go);

            float cnew = fv * creg + iv * gv;
            float hnew = ov * fast_tanh(cnew);
            creg = cnew;

            __half hh16 = __float2half(hnew);
            g_hh[pout][bcell * HDIM + hcol] = hh16;
            g_hl[pout][bcell * HDIM + hcol] =
                __float2half(hnew - __half2float(hh16));

            size_t oidx = ((size_t)bcell * SEQ + t) * HDIM + hcol;
            __stcs(Hout + oidx, hnew);
            __stcs(Cout + oidx, cnew);
        }

        if (t + 1 < SEQ) {
            size_t xb = ((size_t)bcell * SEQ + (t + 1)) * G4 + hcol;
            xgi = __ldcs(g_xg + xb);
            xgf = __ldcs(g_xg + xb + 1024);
            xgg = __ldcs(g_xg + xb + 2048);
            xgo = __ldcs(g_xg + xb + 3072);

            __syncthreads();
            if (tid == 0) {
                __threadfence();
                atomicAdd(&g_bar, 1u);
                unsigned target = 128u * (unsigned)(t + 1);
                while (ld_acq(&g_bar) < target) __nanosleep(32);
            }
            __syncthreads();
        }
    }
}

// ---------------- launch ----------------
extern "C" void kernel_launch(void* const* d_in, const int* in_sizes, int n_in,
                              void* d_out, int out_size) {
    const float* x    = (const float*)d_in[0];
    const float* Wih  = (const float*)d_in[1];
    const float* Whh  = (const float*)d_in[2];
    const float* bih  = (const float*)d_in[3];
    const float* bhh  = (const float*)d_in[4];

    float* Hout = (float*)d_out;
    float* Cout = Hout + (size_t)BATCH * SEQ * HDIM;

    cudaFuncSetAttribute(gemm_input_tc,   cudaFuncAttributeMaxDynamicSharedMemorySize, GI_SMEM);
    cudaFuncSetAttribute(lstm_persistent, cudaFuncAttributeMaxDynamicSharedMemorySize, PS_SMEM);

    init_state_kernel<<<(BATCH * HDIM + 255) / 256, 256>>>();
    convert_x_kernel<<<(int)(((size_t)M_TOTAL * IDIM + 255) / 256), 256>>>(x);
    convert_wih_kernel<<<(int)(((size_t)G4 * IDIM + 255) / 256), 256>>>(Wih);
    convert_whh_kernel<<<(int)(((size_t)G4 * HDIM + 255) / 256), 256>>>(Whh);

    dim3 g1(M_TOTAL / 128, G4 / 128);   // 256 x 32
    gemm_input_tc<<<g1, 256, GI_SMEM>>>(bih, bhh);

    lstm_persistent<<<128, 512, PS_SMEM>>>(Hout, Cout);
}

// round 9
// speedup vs baseline: 8.6813x; 1.1937x over previous
#include <cuda_runtime.h>
#include <cuda_bf16.h>
#include <cuda_fp16.h>
#include <stdint.h>

#define BATCH 64
#define SEQ   512
#define IDIM  1024
#define HDIM  1024
#define G4    4096
#define M_TOTAL (BATCH*SEQ)

// ---------------- scratch (no cudaMalloc allowed) ----------------
__device__ float g_xg[(size_t)M_TOTAL * G4];
__device__ __align__(16) __half g_xh[(size_t)M_TOTAL * IDIM];   // x fp16 hi
__device__ __align__(16) __half g_xl[(size_t)M_TOTAL * IDIM];   // x fp16 lo
__device__ __align__(16) __half g_Wihf[(size_t)G4 * IDIM];      // W_ih fp16
__device__ __align__(16) __half g_Wf[(size_t)G4 * HDIM];        // rearranged W_hh fp16
__device__ __align__(16) __half g_hh[2][BATCH * HDIM];          // h state fp16 (ping-pong)
__device__ unsigned g_ck[4 * 32];                               // per-chunk flags (128B apart)

// ---------------- PTX helpers (base compute_103-safe) ----------------
__device__ __forceinline__ uint32_t smem_u32(const void* p) {
    return (uint32_t)__cvta_generic_to_shared(p);
}
__device__ __forceinline__ void ldmx4(uint32_t r[4], uint32_t addr) {
    asm volatile("ldmatrix.sync.aligned.m8n8.x4.shared.b16 {%0,%1,%2,%3}, [%4];"
        : "=r"(r[0]), "=r"(r[1]), "=r"(r[2]), "=r"(r[3]) : "r"(addr));
}
__device__ __forceinline__ void mma_f16(float c[4], const uint32_t a[4],
                                        uint32_t b0, uint32_t b1) {
    asm volatile("mma.sync.aligned.m16n8k16.row.col.f32.f16.f16.f32 "
        "{%0,%1,%2,%3}, {%4,%5,%6,%7}, {%8,%9}, {%0,%1,%2,%3};"
        : "+f"(c[0]), "+f"(c[1]), "+f"(c[2]), "+f"(c[3])
        : "r"(a[0]), "r"(a[1]), "r"(a[2]), "r"(a[3]), "r"(b0), "r"(b1));
}
__device__ __forceinline__ void cp16(uint32_t dst, const void* src) {
    asm volatile("cp.async.cg.shared.global [%0], [%1], 16;" :: "r"(dst), "l"(src));
}
#define CP_COMMIT() asm volatile("cp.async.commit_group;" ::: "memory")
#define CP_WAIT1()  asm volatile("cp.async.wait_group 1;" ::: "memory")
#define CP_WAIT0()  asm volatile("cp.async.wait_group 0;" ::: "memory")

__device__ __forceinline__ unsigned ld_acq(const unsigned* p) {
    unsigned v;
    asm volatile("ld.acquire.gpu.u32 %0, [%1];" : "=r"(v) : "l"(p) : "memory");
    return v;
}
__device__ __forceinline__ void red_release(unsigned* p, unsigned v) {
    asm volatile("red.add.release.gpu.global.u32 [%0], %1;" :: "l"(p), "r"(v) : "memory");
}

// ---------------- MUFU-free activations ----------------
__device__ __forceinline__ float fast_rcp(float q) {
    float r = __uint_as_float(0x7EF311C2u - __float_as_uint(q));
    r = r * (2.0f - q * r);
    r = r * (2.0f - q * r);
    r = r * (2.0f - q * r);
    return r;
}
__device__ __forceinline__ float fast_tanh(float x) {
    x = fminf(fmaxf(x, -7.90531110763549805f), 7.90531110763549805f);
    float s = x * x;
    float p = fmaf(s, -2.76076847742355e-16f, 2.00018790482477e-13f);
    p = fmaf(p, s, -8.60467152213735e-11f);
    p = fmaf(p, s,  5.12229709037114e-08f);
    p = fmaf(p, s,  1.48572235717979e-05f);
    p = fmaf(p, s,  6.37261928875436e-04f);
    p = fmaf(p, s,  4.89352455891786e-03f);
    p = x * p;
    float q = fmaf(s, 1.19825839466702e-06f, 1.18534705686654e-04f);
    q = fmaf(q, s, 2.26843463243900e-03f);
    q = fmaf(q, s, 4.89352518554385e-03f);
    return p * fast_rcp(q);
}
__device__ __forceinline__ float fast_sigmoid(float x) {
    return fmaf(fast_tanh(0.5f * x), 0.5f, 0.5f);
}

// ---------------- init + converts ----------------
__global__ void init_state_kernel() {
    int i = blockIdx.x * blockDim.x + threadIdx.x;
    if (i < 4 * 32) g_ck[i] = 0u;
    if (i < BATCH * HDIM) {
        __half z = __float2half(0.f);
        g_hh[0][i] = z; g_hh[1][i] = z;
    }
}
__global__ void convert_x_kernel(const float* __restrict__ x) {
    size_t i = (size_t)blockIdx.x * blockDim.x + threadIdx.x;
    if (i >= (size_t)M_TOTAL * IDIM) return;
    float v = x[i];
    __half h = __float2half(v);
    g_xh[i] = h;
    g_xl[i] = __float2half(v - __half2float(h));
}
__global__ void convert_wih_kernel(const float* __restrict__ W) {
    size_t i = (size_t)blockIdx.x * blockDim.x + threadIdx.x;
    if (i >= (size_t)G4 * IDIM) return;
    g_Wihf[i] = __float2half(W[i]);
}
// W_hh rearrange (fp16): out_row = blk*32 + g*8 + hl  <-  in_row = g*1024 + blk*8 + hl
__global__ void convert_whh_kernel(const float* __restrict__ Whh) {
    size_t idx = (size_t)blockIdx.x * blockDim.x + threadIdx.x;
    if (idx >= (size_t)G4 * HDIM) return;
    int out_row = (int)(idx >> 10);
    int k   = (int)(idx & 1023);
    int blk = out_row >> 5;
    int lg  = out_row & 31;
    int in_row = (lg >> 3) * HDIM + blk * 8 + (lg & 7);
    g_Wf[idx] = __float2half(Whh[(size_t)in_row * HDIM + k]);
}

// ---------------- input projection GEMM (fp16 2-combo HMMA) ----------------
// xg[m][n] = x[m][:] . Wih[n][:] + bih[n]+bhh[n]; block 128x128, K-chunk 32.
#define GI_AHI   0
#define GI_ALO   10240
#define GI_B     20480
#define GI_STAGE 30720
#define GI_SMEM  (3*GI_STAGE)     // 92160

__global__ void __launch_bounds__(256, 1)
gemm_input_tc(const float* __restrict__ bih, const float* __restrict__ bhh) {
    extern __shared__ char smem[];
    const uint32_t sb = smem_u32(smem);
    const int tid = threadIdx.x, wid = tid >> 5, lane = tid & 31;
    const int mbase = blockIdx.x * 128;
    const int nbase = blockIdx.y * 128;
    const int wm = wid & 1, wn = wid >> 1;

    float acc[4][4][4] = {};

#define GI_ISSUE(i) do {                                                      \
    uint32_t st = sb + ((i) % 3) * GI_STAGE;                                  \
    _Pragma("unroll")                                                         \
    for (int p = 0; p < 2; p++) {                                             \
        int u = tid + p * 256; int r = u >> 2, c = u & 3;                     \
        size_t g = (size_t)(mbase + r) * IDIM + (size_t)(i) * 32 + c * 8;     \
        cp16(st + GI_AHI + r * 80 + c * 16, g_xh + g);                        \
        cp16(st + GI_ALO + r * 80 + c * 16, g_xl + g);                        \
    }                                                                         \
    _Pragma("unroll")                                                         \
    for (int p = 0; p < 2; p++) {                                             \
        int u = tid + p * 256; int r = u >> 2, c = u & 3;                     \
        size_t g = (size_t)(nbase + r) * IDIM + (size_t)(i) * 32 + c * 8;     \
        cp16(st + GI_B + r * 80 + c * 16, g_Wihf + g);                        \
    }                                                                         \
} while (0)

    GI_ISSUE(0); CP_COMMIT();
    GI_ISSUE(1); CP_COMMIT();

    for (int i = 0; i < 32; i++) {
        CP_WAIT1();
        __syncthreads();
        if (i + 2 < 32) GI_ISSUE(i + 2);
        CP_COMMIT();

        uint32_t st = sb + (i % 3) * GI_STAGE;
#pragma unroll
        for (int kk = 0; kk < 2; kk++) {
            const int colb = kk * 16 + ((lane >> 4) << 3);
            uint32_t ah[4][4], al[4][4], b[2][4];
#pragma unroll
            for (int mt = 0; mt < 4; mt++) {
                int row = wm * 64 + mt * 16 + (lane & 15);
                uint32_t a = st + GI_AHI + row * 80 + colb * 2;
                ldmx4(ah[mt], a);
                ldmx4(al[mt], a + (GI_ALO - GI_AHI));
            }
#pragma unroll
            for (int bt = 0; bt < 2; bt++) {
                int row = wn * 32 + bt * 16 + (lane & 15);
                ldmx4(b[bt], st + GI_B + row * 80 + colb * 2);
            }
#pragma unroll
            for (int mt = 0; mt < 4; mt++)
#pragma unroll
                for (int nt = 0; nt < 4; nt++) {
                    int bt = nt >> 1, ns = nt & 1;
                    mma_f16(acc[mt][nt], ah[mt], b[bt][ns], b[bt][ns + 2]);
                    mma_f16(acc[mt][nt], al[mt], b[bt][ns], b[bt][ns + 2]);
                }
        }
    }

#pragma unroll
    for (int mt = 0; mt < 4; mt++) {
        int m0 = mbase + wm * 64 + mt * 16 + (lane >> 2);
#pragma unroll
        for (int nt = 0; nt < 4; nt++) {
            int n = nbase + wn * 32 + nt * 8 + (lane & 3) * 2;
            float b0 = bih[n] + bhh[n];
            float b1 = bih[n + 1] + bhh[n + 1];
            __stcs((float2*)(g_xg + (size_t)m0 * G4 + n),
                   make_float2(acc[mt][nt][0] + b0, acc[mt][nt][1] + b1));
            __stcs((float2*)(g_xg + (size_t)(m0 + 8) * G4 + n),
                   make_float2(acc[mt][nt][2] + b0, acc[mt][nt][3] + b1));
        }
    }
}

// ---------------- persistent LSTM step kernel (fp16, flag dataflow) --------
// Grid 128, 512 threads. Block owns 32 W rows (4 gates x 8 hcols).
// W fp16 slice (66KB) resident; per step: 4 K-chunks of 256, h fp16 streamed
// 3-stage, each chunk gated on its producer flag (blocks 32ch..32ch+31).
// Warps: wm(2: 16 rows) x wn(2: 32 batches) x kw(4: K64 of each chunk).
// Row stride 528B -> conflict-free 8-row LDSM phases.
#define PS_W      0
#define PS_WCH    16896                  // 32 rows * 528B per chunk
#define PS_H      67584                  // 4 * PS_WCH
#define PS_HSTAGE 33792                  // 64 rows * 528B
#define PS_SMEM   (PS_H + 3*PS_HSTAGE)   // 168960

__global__ void __launch_bounds__(512, 1)
lstm_persistent(float* __restrict__ Hout, float* __restrict__ Cout) {
    extern __shared__ char smem[];
    const uint32_t sb = smem_u32(smem);
    const int tid = threadIdx.x, wid = tid >> 5, lane = tid & 31;
    const int blk = blockIdx.x;
    const int wm = wid & 1;            // M half (16 rows)
    const int wn = (wid >> 1) & 1;     // N half (32 batches)
    const int kw = wid >> 2;           // K quarter of chunk (64)
    const int myck = blk >> 5;         // chunk this block produces

    // ---- preload W slice fp16: 4 chunks x 32 rows x 256 k ----
#pragma unroll
    for (int p = 0; p < 8; p++) {
        int u = tid + p * 512;
        int ch = u >> 10, r = (u >> 5) & 31, c = u & 31;
        size_t g = (size_t)(blk * 32 + r) * HDIM + ch * 256 + c * 8;
        cp16(sb + PS_W + ch * PS_WCH + r * 528 + c * 16, g_Wf + g);
    }
    CP_COMMIT();
    CP_WAIT0();
    __syncthreads();

    float* sg = (float*)(smem + PS_H);   // [4 kw][32 rows][68] overlays stages

    const int hl = tid & 7;
    const int bcell = tid >> 3;
    const int hcol = blk * 8 + hl;
    float creg = 0.f;

    float xgi, xgf, xgg, xgo;
    {
        size_t xb = ((size_t)bcell * SEQ + 0) * G4 + hcol;
        xgi = __ldcs(g_xg + xb);
        xgf = __ldcs(g_xg + xb + 1024);
        xgg = __ldcs(g_xg + xb + 2048);
        xgo = __ldcs(g_xg + xb + 3072);
    }

    for (int t = 0; t < SEQ; t++) {
        const int pin = t & 1, pout = pin ^ 1;
        const __half* hhp = g_hh[pin];
        const unsigned tgt = 32u * (unsigned)t;   // flags from steps < t

        float acc[4][4] = {};

#define PS_ISSUE(i) do {                                                     \
    if ((tid & 31) == 0) {                                                   \
        const unsigned* fp = &g_ck[(i) * 32];                                \
        while (ld_acq(fp) < tgt) __nanosleep(64);                            \
    }                                                                        \
    __syncwarp();                                                            \
    uint32_t st = sb + PS_H + ((i) % 3) * PS_HSTAGE;                         \
    _Pragma("unroll")                                                        \
    for (int p = 0; p < 4; p++) {                                            \
        int u = tid + p * 512; int r = u >> 5, c = u & 31;                   \
        size_t g = (size_t)r * HDIM + (size_t)(i) * 256 + c * 8;             \
        cp16(st + r * 528 + c * 16, hhp + g);                                \
    }                                                                        \
} while (0)

        PS_ISSUE(0); CP_COMMIT();
        PS_ISSUE(1); CP_COMMIT();

        for (int i = 0; i < 4; i++) {
            CP_WAIT1();
            __syncthreads();
            if (i + 2 < 4) PS_ISSUE(i + 2);
            CP_COMMIT();

            uint32_t hstg  = sb + PS_H + (i % 3) * PS_HSTAGE;
            uint32_t wbase = sb + PS_W + i * PS_WCH;

            uint32_t b[2][4][4];   // [nb(16 batches)][kk(k16)]
#pragma unroll
            for (int nb = 0; nb < 2; nb++)
#pragma unroll
                for (int kk = 0; kk < 4; kk++)
                    ldmx4(b[nb][kk],
                          hstg + (wn * 32 + nb * 16 + (lane & 15)) * 528
                               + (kw * 64 + kk * 16 + (lane >> 4) * 8) * 2);
#pragma unroll
            for (int kk = 0; kk < 4; kk++) {
                uint32_t a[4];
                ldmx4(a, wbase + (wm * 16 + (lane & 15)) * 528
                              + (kw * 64 + kk * 16 + (lane >> 4) * 8) * 2);
#pragma unroll
                for (int nb = 0; nb < 2; nb++)
#pragma unroll
                    for (int ns = 0; ns < 2; ns++)
                        mma_f16(acc[nb * 2 + ns], a, b[nb][kk][ns], b[nb][kk][ns + 2]);
            }
        }

        __syncthreads();           // all stage reads done; stages reused as sg

        // gate exchange: sg[kw][row 0..31][batch 0..63]
        {
            int row = wm * 16 + (lane >> 2);
            float* base = sg + kw * 2176;
#pragma unroll
            for (int nb = 0; nb < 2; nb++)
#pragma unroll
                for (int ns = 0; ns < 2; ns++) {
                    int ai = nb * 2 + ns;
                    int col = wn * 32 + nb * 16 + ns * 8 + (lane & 3) * 2;
                    base[row * 68 + col]           = acc[ai][0];
                    base[row * 68 + col + 1]       = acc[ai][1];
                    base[(row + 8) * 68 + col]     = acc[ai][2];
                    base[(row + 8) * 68 + col + 1] = acc[ai][3];
                }
        }
        __syncthreads();

        // cell update (1 cell/thread, c in register); sum 4 kw partials
        {
            float gi = xgi, gf = xgf, gg = xgg, go = xgo;
#pragma unroll
            for (int k = 0; k < 4; k++) {
                const float* base = sg + k * 2176;
                gi += base[(0 * 8 + hl) * 68 + bcell];
                gf += base[(1 * 8 + hl) * 68 + bcell];
                gg += base[(2 * 8 + hl) * 68 + bcell];
                go += base[(3 * 8 + hl) * 68 + bcell];
            }

            float iv = fast_sigmoid(gi);
            float fv = fast_sigmoid(gf);
            float gv = fast_tanh(gg);
            float ov = fast_sigmoid(go);

            float cnew = fv * creg + iv * gv;
            float hnew = ov * fast_tanh(cnew);
            creg = cnew;

            g_hh[pout][bcell * HDIM + hcol] = __float2half(hnew);

            size_t oidx = ((size_t)bcell * SEQ + t) * HDIM + hcol;
            __stcs(Hout + oidx, hnew);
            __stcs(Cout + oidx, cnew);
        }

        // xg prefetch for t+1 (overlaps flag waits of next step)
        if (t + 1 < SEQ) {
            size_t xb = ((size_t)bcell * SEQ + (t + 1)) * G4 + hcol;
            xgi = __ldcs(g_xg + xb);
            xgf = __ldcs(g_xg + xb + 1024);
            xgg = __ldcs(g_xg + xb + 2048);
            xgo = __ldcs(g_xg + xb + 3072);
        }

        __syncthreads();           // h stores + sg reads complete block-wide
        if (tid == 0) red_release(&g_ck[myck * 32], 1u);
    }
}

// ---------------- launch ----------------
extern "C" void kernel_launch(void* const* d_in, const int* in_sizes, int n_in,
                              void* d_out, int out_size) {
    const float* x    = (const float*)d_in[0];
    const float* Wih  = (const float*)d_in[1];
    const float* Whh  = (const float*)d_in[2];
    const float* bih  = (const float*)d_in[3];
    const float* bhh  = (const float*)d_in[4];

    float* Hout = (float*)d_out;
    float* Cout = Hout + (size_t)BATCH * SEQ * HDIM;

    cudaFuncSetAttribute(gemm_input_tc,   cudaFuncAttributeMaxDynamicSharedMemorySize, GI_SMEM);
    cudaFuncSetAttribute(lstm_persistent, cudaFuncAttributeMaxDynamicSharedMemorySize, PS_SMEM);

    init_state_kernel<<<(BATCH * HDIM + 255) / 256, 256>>>();
    convert_x_kernel<<<(int)(((size_t)M_TOTAL * IDIM + 255) / 256), 256>>>(x);
    convert_wih_kernel<<<(int)(((size_t)G4 * IDIM + 255) / 256), 256>>>(Wih);
    convert_whh_kernel<<<(int)(((size_t)G4 * HDIM + 255) / 256), 256>>>(Whh);

    dim3 g1(M_TOTAL / 128, G4 / 128);   // 256 x 32
    gemm_input_tc<<<g1, 256, GI_SMEM>>>(bih, bhh);

    lstm_persistent<<<128, 512, PS_SMEM>>>(Hout, Cout);
}

// round 10
// speedup vs baseline: 12.7627x; 1.4701x over previous
#include <cuda_runtime.h>
#include <cuda_bf16.h>
#include <cuda_fp16.h>
#include <stdint.h>

#define BATCH 64
#define SEQ   512
#define IDIM  1024
#define HDIM  1024
#define G4    4096
#define M_TOTAL (BATCH*SEQ)

// ---------------- scratch (no cudaMalloc allowed) ----------------
__device__ float g_xg[(size_t)M_TOTAL * G4];
__device__ __align__(16) __half g_xh[(size_t)M_TOTAL * IDIM];   // x fp16
__device__ __align__(16) __half g_Wihf[(size_t)G4 * IDIM];      // W_ih fp16
__device__ __align__(16) __half g_Wf[(size_t)G4 * HDIM];        // rearranged W_hh fp16
__device__ __align__(16) __half g_hh[2][BATCH * HDIM];          // h state fp16 (ping-pong)
__device__ unsigned g_ck[4 * 32];                               // per-chunk flags (128B apart)

// ---------------- PTX helpers (base compute_103-safe) ----------------
__device__ __forceinline__ uint32_t smem_u32(const void* p) {
    return (uint32_t)__cvta_generic_to_shared(p);
}
__device__ __forceinline__ void ldmx4(uint32_t r[4], uint32_t addr) {
    asm volatile("ldmatrix.sync.aligned.m8n8.x4.shared.b16 {%0,%1,%2,%3}, [%4];"
        : "=r"(r[0]), "=r"(r[1]), "=r"(r[2]), "=r"(r[3]) : "r"(addr));
}
__device__ __forceinline__ void mma_f16(float c[4], const uint32_t a[4],
                                        uint32_t b0, uint32_t b1) {
    asm volatile("mma.sync.aligned.m16n8k16.row.col.f32.f16.f16.f32 "
        "{%0,%1,%2,%3}, {%4,%5,%6,%7}, {%8,%9}, {%0,%1,%2,%3};"
        : "+f"(c[0]), "+f"(c[1]), "+f"(c[2]), "+f"(c[3])
        : "r"(a[0]), "r"(a[1]), "r"(a[2]), "r"(a[3]), "r"(b0), "r"(b1));
}
__device__ __forceinline__ void cp16(uint32_t dst, const void* src) {
    asm volatile("cp.async.cg.shared.global [%0], [%1], 16;" :: "r"(dst), "l"(src));
}
#define CP_COMMIT() asm volatile("cp.async.commit_group;" ::: "memory")
#define CP_WAIT1()  asm volatile("cp.async.wait_group 1;" ::: "memory")
#define CP_WAIT0()  asm volatile("cp.async.wait_group 0;" ::: "memory")

__device__ __forceinline__ unsigned ld_acq(const unsigned* p) {
    unsigned v;
    asm volatile("ld.acquire.gpu.u32 %0, [%1];" : "=r"(v) : "l"(p) : "memory");
    return v;
}
__device__ __forceinline__ void red_release(unsigned* p, unsigned v) {
    asm volatile("red.add.release.gpu.global.u32 [%0], %1;" :: "l"(p), "r"(v) : "memory");
}

// ---------------- MUFU-free activations ----------------
__device__ __forceinline__ float fast_rcp(float q) {
    float r = __uint_as_float(0x7EF311C2u - __float_as_uint(q));
    r = r * (2.0f - q * r);
    r = r * (2.0f - q * r);
    r = r * (2.0f - q * r);
    return r;
}
__device__ __forceinline__ float fast_tanh(float x) {
    x = fminf(fmaxf(x, -7.90531110763549805f), 7.90531110763549805f);
    float s = x * x;
    float p = fmaf(s, -2.76076847742355e-16f, 2.00018790482477e-13f);
    p = fmaf(p, s, -8.60467152213735e-11f);
    p = fmaf(p, s,  5.12229709037114e-08f);
    p = fmaf(p, s,  1.48572235717979e-05f);
    p = fmaf(p, s,  6.37261928875436e-04f);
    p = fmaf(p, s,  4.89352455891786e-03f);
    p = x * p;
    float q = fmaf(s, 1.19825839466702e-06f, 1.18534705686654e-04f);
    q = fmaf(q, s, 2.26843463243900e-03f);
    q = fmaf(q, s, 4.89352518554385e-03f);
    return p * fast_rcp(q);
}
__device__ __forceinline__ float fast_sigmoid(float x) {
    return fmaf(fast_tanh(0.5f * x), 0.5f, 0.5f);
}

// ---------------- init + converts ----------------
__global__ void init_state_kernel() {
    int i = blockIdx.x * blockDim.x + threadIdx.x;
    if (i < 4 * 32) g_ck[i] = 0u;
    if (i < BATCH * HDIM) {
        __half z = __float2half(0.f);
        g_hh[0][i] = z; g_hh[1][i] = z;
    }
}
__global__ void convert_x_kernel(const float* __restrict__ x) {
    size_t i = (size_t)blockIdx.x * blockDim.x + threadIdx.x;
    if (i >= (size_t)M_TOTAL * IDIM) return;
    g_xh[i] = __float2half(x[i]);
}
__global__ void convert_wih_kernel(const float* __restrict__ W) {
    size_t i = (size_t)blockIdx.x * blockDim.x + threadIdx.x;
    if (i >= (size_t)G4 * IDIM) return;
    g_Wihf[i] = __float2half(W[i]);
}
// W_hh rearrange (fp16): out_row = blk*32 + g*8 + hl  <-  in_row = g*1024 + blk*8 + hl
__global__ void convert_whh_kernel(const float* __restrict__ Whh) {
    size_t idx = (size_t)blockIdx.x * blockDim.x + threadIdx.x;
    if (idx >= (size_t)G4 * HDIM) return;
    int out_row = (int)(idx >> 10);
    int k   = (int)(idx & 1023);
    int blk = out_row >> 5;
    int lg  = out_row & 31;
    int in_row = (lg >> 3) * HDIM + blk * 8 + (lg & 7);
    g_Wf[idx] = __float2half(Whh[(size_t)in_row * HDIM + k]);
}

// ---------------- input projection GEMM (plain fp16 HMMA) ----------------
// xg[m][n] = x[m][:] . Wih[n][:] + bih[n]+bhh[n]; block 128x128, K-chunk 32.
#define GI_A     0
#define GI_B     10240
#define GI_STAGE 20480
#define GI_SMEM  (3*GI_STAGE)     // 61440

__global__ void __launch_bounds__(256, 1)
gemm_input_tc(const float* __restrict__ bih, const float* __restrict__ bhh) {
    extern __shared__ char smem[];
    const uint32_t sb = smem_u32(smem);
    const int tid = threadIdx.x, wid = tid >> 5, lane = tid & 31;
    const int mbase = blockIdx.x * 128;
    const int nbase = blockIdx.y * 128;
    const int wm = wid & 1, wn = wid >> 1;

    float acc[4][4][4] = {};

#define GI_ISSUE(i) do {                                                      \
    uint32_t st = sb + ((i) % 3) * GI_STAGE;                                  \
    _Pragma("unroll")                                                         \
    for (int p = 0; p < 2; p++) {                                             \
        int u = tid + p * 256; int r = u >> 2, c = u & 3;                     \
        size_t g = (size_t)(mbase + r) * IDIM + (size_t)(i) * 32 + c * 8;     \
        cp16(st + GI_A + r * 80 + c * 16, g_xh + g);                          \
    }                                                                         \
    _Pragma("unroll")                                                         \
    for (int p = 0; p < 2; p++) {                                             \
        int u = tid + p * 256; int r = u >> 2, c = u & 3;                     \
        size_t g = (size_t)(nbase + r) * IDIM + (size_t)(i) * 32 + c * 8;     \
        cp16(st + GI_B + r * 80 + c * 16, g_Wihf + g);                        \
    }                                                                         \
} while (0)

    GI_ISSUE(0); CP_COMMIT();
    GI_ISSUE(1); CP_COMMIT();

    for (int i = 0; i < 32; i++) {
        CP_WAIT1();
        __syncthreads();
        if (i + 2 < 32) GI_ISSUE(i + 2);
        CP_COMMIT();

        uint32_t st = sb + (i % 3) * GI_STAGE;
#pragma unroll
        for (int kk = 0; kk < 2; kk++) {
            const int colb = kk * 16 + ((lane >> 4) << 3);
            uint32_t a[4][4], b[2][4];
#pragma unroll
            for (int mt = 0; mt < 4; mt++) {
                int row = wm * 64 + mt * 16 + (lane & 15);
                ldmx4(a[mt], st + GI_A + row * 80 + colb * 2);
            }
#pragma unroll
            for (int bt = 0; bt < 2; bt++) {
                int row = wn * 32 + bt * 16 + (lane & 15);
                ldmx4(b[bt], st + GI_B + row * 80 + colb * 2);
            }
#pragma unroll
            for (int mt = 0; mt < 4; mt++)
#pragma unroll
                for (int nt = 0; nt < 4; nt++) {
                    int bt = nt >> 1, ns = nt & 1;
                    mma_f16(acc[mt][nt], a[mt], b[bt][ns], b[bt][ns + 2]);
                }
        }
    }

#pragma unroll
    for (int mt = 0; mt < 4; mt++) {
        int m0 = mbase + wm * 64 + mt * 16 + (lane >> 2);
#pragma unroll
        for (int nt = 0; nt < 4; nt++) {
            int n = nbase + wn * 32 + nt * 8 + (lane & 3) * 2;
            float b0 = bih[n] + bhh[n];
            float b1 = bih[n + 1] + bhh[n + 1];
            __stcs((float2*)(g_xg + (size_t)m0 * G4 + n),
                   make_float2(acc[mt][nt][0] + b0, acc[mt][nt][1] + b1));
            __stcs((float2*)(g_xg + (size_t)(m0 + 8) * G4 + n),
                   make_float2(acc[mt][nt][2] + b0, acc[mt][nt][3] + b1));
        }
    }
}

// ---------------- persistent LSTM step kernel (fp16, flag dataflow) --------
// Grid 128, 512 threads. Block owns 32 W rows (4 gates x 8 hcols).
// W fp16 slice (66KB) resident; per step: 4 K-chunks of 256, h fp16 streamed
// 3-stage. One consolidated flag wait per step (tid 0..3, one flag each,
// hot spin), then the pipeline runs with no further waits.
// Warps: wm(2: 16 rows) x wn(2: 32 batches) x kw(4: K64 of each chunk).
// Row stride 528B -> conflict-free 8-row LDSM phases.
#define PS_W      0
#define PS_WCH    16896                  // 32 rows * 528B per chunk
#define PS_H      67584                  // 4 * PS_WCH
#define PS_HSTAGE 33792                  // 64 rows * 528B
#define PS_SG     (PS_H + 3*PS_HSTAGE)   // 168960 (dedicated gate-exchange)
#define PS_SMEM   (PS_SG + 4*2176*4)     // 203776

__global__ void __launch_bounds__(512, 1)
lstm_persistent(float* __restrict__ Hout, float* __restrict__ Cout) {
    extern __shared__ char smem[];
    const uint32_t sb = smem_u32(smem);
    const int tid = threadIdx.x, wid = tid >> 5, lane = tid & 31;
    const int blk = blockIdx.x;
    const int wm = wid & 1;            // M half (16 rows)
    const int wn = (wid >> 1) & 1;     // N half (32 batches)
    const int kw = wid >> 2;           // K quarter of chunk (64)
    const int myck = blk >> 5;         // chunk this block produces

    // ---- preload W slice fp16: 4 chunks x 32 rows x 256 k ----
#pragma unroll
    for (int p = 0; p < 8; p++) {
        int u = tid + p * 512;
        int ch = u >> 10, r = (u >> 5) & 31, c = u & 31;
        size_t g = (size_t)(blk * 32 + r) * HDIM + ch * 256 + c * 8;
        cp16(sb + PS_W + ch * PS_WCH + r * 528 + c * 16, g_Wf + g);
    }
    CP_COMMIT();
    CP_WAIT0();
    __syncthreads();

    float* sg = (float*)(smem + PS_SG);   // [4 kw][32 rows][68], dedicated

    const int hl = tid & 7;
    const int bcell = tid >> 3;
    const int hcol = blk * 8 + hl;
    float creg = 0.f;

    float xgi, xgf, xgg, xgo;
    {
        size_t xb = ((size_t)bcell * SEQ + 0) * G4 + hcol;
        xgi = __ldcs(g_xg + xb);
        xgf = __ldcs(g_xg + xb + 1024);
        xgg = __ldcs(g_xg + xb + 2048);
        xgo = __ldcs(g_xg + xb + 3072);
    }

    for (int t = 0; t < SEQ; t++) {
        const int pin = t & 1, pout = pin ^ 1;
        const __half* hhp = g_hh[pin];

        // ---- consolidated flag wait: all 4 chunks ready before pipeline ----
        if (tid < 4) {
            const unsigned tgt = 32u * (unsigned)t;
            const unsigned* fp = &g_ck[tid * 32];
            while (ld_acq(fp) < tgt) {}
        }
        __syncthreads();

        float acc[4][4] = {};

#define PS_ISSUE(i) do {                                                     \
    uint32_t st = sb + PS_H + ((i) % 3) * PS_HSTAGE;                         \
    _Pragma("unroll")                                                        \
    for (int p = 0; p < 4; p++) {                                            \
        int u = tid + p * 512; int r = u >> 5, c = u & 31;                   \
        size_t g = (size_t)r * HDIM + (size_t)(i) * 256 + c * 8;             \
        cp16(st + r * 528 + c * 16, hhp + g);                                \
    }                                                                        \
} while (0)

        PS_ISSUE(0); CP_COMMIT();
        PS_ISSUE(1); CP_COMMIT();

        for (int i = 0; i < 4; i++) {
            CP_WAIT1();
            __syncthreads();
            if (i + 2 < 4) PS_ISSUE(i + 2);
            CP_COMMIT();

            uint32_t hstg  = sb + PS_H + (i % 3) * PS_HSTAGE;
            uint32_t wbase = sb + PS_W + i * PS_WCH;

            uint32_t b[2][4][4];   // [nb(16 batches)][kk(k16)]
#pragma unroll
            for (int nb = 0; nb < 2; nb++)
#pragma unroll
                for (int kk = 0; kk < 4; kk++)
                    ldmx4(b[nb][kk],
                          hstg + (wn * 32 + nb * 16 + (lane & 15)) * 528
                               + (kw * 64 + kk * 16 + (lane >> 4) * 8) * 2);
#pragma unroll
            for (int kk = 0; kk < 4; kk++) {
                uint32_t a[4];
                ldmx4(a, wbase + (wm * 16 + (lane & 15)) * 528
                              + (kw * 64 + kk * 16 + (lane >> 4) * 8) * 2);
#pragma unroll
                for (int nb = 0; nb < 2; nb++)
#pragma unroll
                    for (int ns = 0; ns < 2; ns++)
                        mma_f16(acc[nb * 2 + ns], a, b[nb][kk][ns], b[nb][kk][ns + 2]);
            }
        }

        // gate exchange (dedicated sg: no WAR with stages, no extra sync)
        {
            int row = wm * 16 + (lane >> 2);
            float* base = sg + kw * 2176;
#pragma unroll
            for (int nb = 0; nb < 2; nb++)
#pragma unroll
                for (int ns = 0; ns < 2; ns++) {
                    int ai = nb * 2 + ns;
                    int col = wn * 32 + nb * 16 + ns * 8 + (lane & 3) * 2;
                    base[row * 68 + col]           = acc[ai][0];
                    base[row * 68 + col + 1]       = acc[ai][1];
                    base[(row + 8) * 68 + col]     = acc[ai][2];
                    base[(row + 8) * 68 + col + 1] = acc[ai][3];
                }
        }
        __syncthreads();

        // cell update (1 cell/thread, c in register); sum 4 kw partials
        float hnew, cnew;
        {
            float gi = xgi, gf = xgf, gg = xgg, go = xgo;
#pragma unroll
            for (int k = 0; k < 4; k++) {
                const float* base = sg + k * 2176;
                gi += base[(0 * 8 + hl) * 68 + bcell];
                gf += base[(1 * 8 + hl) * 68 + bcell];
                gg += base[(2 * 8 + hl) * 68 + bcell];
                go += base[(3 * 8 + hl) * 68 + bcell];
            }

            float iv = fast_sigmoid(gi);
            float fv = fast_sigmoid(gf);
            float gv = fast_tanh(gg);
            float ov = fast_sigmoid(go);

            cnew = fv * creg + iv * gv;
            hnew = ov * fast_tanh(cnew);
            creg = cnew;

            g_hh[pout][bcell * HDIM + hcol] = __float2half(hnew);
        }
        __syncthreads();           // all h stores + sg reads complete

        // post flag FIRST (wakes consumers), then outputs + prefetch
        if (tid == 0 && t + 1 < SEQ) red_release(&g_ck[myck * 32], 1u);

        size_t oidx = ((size_t)bcell * SEQ + t) * HDIM + hcol;
        __stcs(Hout + oidx, hnew);
        __stcs(Cout + oidx, cnew);

        if (t + 1 < SEQ) {
            size_t xb = ((size_t)bcell * SEQ + (t + 1)) * G4 + hcol;
            xgi = __ldcs(g_xg + xb);
            xgf = __ldcs(g_xg + xb + 1024);
            xgg = __ldcs(g_xg + xb + 2048);
            xgo = __ldcs(g_xg + xb + 3072);
        }
    }
}

// ---------------- launch ----------------
extern "C" void kernel_launch(void* const* d_in, const int* in_sizes, int n_in,
                              void* d_out, int out_size) {
    const float* x    = (const float*)d_in[0];
    const float* Wih  = (const float*)d_in[1];
    const float* Whh  = (const float*)d_in[2];
    const float* bih  = (const float*)d_in[3];
    const float* bhh  = (const float*)d_in[4];

    float* Hout = (float*)d_out;
    float* Cout = Hout + (size_t)BATCH * SEQ * HDIM;

    cudaFuncSetAttribute(gemm_input_tc,   cudaFuncAttributeMaxDynamicSharedMemorySize, GI_SMEM);
    cudaFuncSetAttribute(lstm_persistent, cudaFuncAttributeMaxDynamicSharedMemorySize, PS_SMEM);

    init_state_kernel<<<(BATCH * HDIM + 255) / 256, 256>>>();
    convert_x_kernel<<<(int)(((size_t)M_TOTAL * IDIM + 255) / 256), 256>>>(x);
    convert_wih_kernel<<<(int)(((size_t)G4 * IDIM + 255) / 256), 256>>>(Wih);
    convert_whh_kernel<<<(int)(((size_t)G4 * HDIM + 255) / 256), 256>>>(Whh);

    dim3 g1(M_TOTAL / 128, G4 / 128);   // 256 x 32
    gemm_input_tc<<<g1, 256, GI_SMEM>>>(bih, bhh);

    lstm_persistent<<<128, 512, PS_SMEM>>>(Hout, Cout);
}